// round 1
// baseline (speedup 1.0000x reference)
#include <cuda_runtime.h>
#include <math.h>

#define N_PTS 8192
#define DIM   256
#define NS    5
#define BM    128
#define BK    16

// ---------------- device scratch (no allocations allowed) ----------------
__device__ double g_sum, g_sumsq;
__device__ double g_colsum[DIM];
__device__ unsigned int g_minbits, g_maxbits;
__device__ float  g_rowsq[N_PTS];
__device__ int    g_scales[NS];
__device__ float  g_s2[NS];
__device__ float  g_boxthr[NS];
__device__ float  g_hmin, g_hrange;
__device__ unsigned long long g_box_cnt[NS];
__device__ unsigned long long g_corr_cnt[NS];
__device__ unsigned long long g_hist[NS][16];

// order-preserving float<->uint for atomic min/max
__device__ __forceinline__ unsigned f2mono(float f) {
    unsigned u = __float_as_uint(f);
    return (u & 0x80000000u) ? ~u : (u | 0x80000000u);
}
__device__ __forceinline__ float mono2f(unsigned u) {
    unsigned b = (u & 0x80000000u) ? (u & 0x7fffffffu) : ~u;
    return __uint_as_float(b);
}

// ---------------- K0: zero scratch (graph replays => must re-init) ----------------
__global__ void k_init() {
    int t = threadIdx.x;
    if (t == 0) { g_sum = 0.0; g_sumsq = 0.0; g_minbits = 0xFFFFFFFFu; g_maxbits = 0u; }
    if (t < DIM) g_colsum[t] = 0.0;
    if (t < NS)  { g_box_cnt[t] = 0ull; g_corr_cnt[t] = 0ull; }
    if (t < NS * 16) ((unsigned long long*)g_hist)[t] = 0ull;
}

// ---------------- K1: global sum/sumsq/min/max + per-column sums ----------------
__global__ void k_stats(const float* __restrict__ x) {
    __shared__ double s_sum[256], s_sq[256];
    __shared__ unsigned s_min[256], s_max[256];
    int t = threadIdx.x;
    double ls = 0.0, lq = 0.0, lcol = 0.0;
    unsigned lmin = 0xFFFFFFFFu, lmax = 0u;
    // stride is multiple of 256 => this thread always sees column t
    for (int i = blockIdx.x * 256 + t; i < N_PTS * DIM; i += gridDim.x * 256) {
        float v = x[i];
        ls += v; lq += (double)v * (double)v; lcol += v;
        unsigned m = f2mono(v);
        lmin = min(lmin, m); lmax = max(lmax, m);
    }
    atomicAdd(&g_colsum[t], lcol);
    s_sum[t] = ls; s_sq[t] = lq; s_min[t] = lmin; s_max[t] = lmax;
    __syncthreads();
    for (int o = 128; o; o >>= 1) {
        if (t < o) {
            s_sum[t] += s_sum[t + o]; s_sq[t] += s_sq[t + o];
            s_min[t] = min(s_min[t], s_min[t + o]);
            s_max[t] = max(s_max[t], s_max[t + o]);
        }
        __syncthreads();
    }
    if (t == 0) {
        atomicAdd(&g_sum, s_sum[0]);
        atomicAdd(&g_sumsq, s_sq[0]);
        atomicMin(&g_minbits, s_min[0]);
        atomicMax(&g_maxbits, s_max[0]);
    }
}

// ---------------- K1b: per-row squared norms ----------------
__global__ void k_rowsq(const float* __restrict__ x) {
    int warp = (blockIdx.x * blockDim.x + threadIdx.x) >> 5;
    int lane = threadIdx.x & 31;
    if (warp >= N_PTS) return;
    const float* r = x + warp * DIM;
    float s = 0.f;
    for (int k = lane; k < DIM; k += 32) { float v = r[k]; s += v * v; }
    for (int o = 16; o; o >>= 1) s += __shfl_down_sync(0xffffffffu, s, o);
    if (!lane) g_rowsq[warp] = s;
}

// ---------------- K2: scales + thresholds (1 thread) ----------------
__global__ void k_setup(const float* __restrict__ scale_params) {
    double nd = (double)N_PTS * (double)DIM;
    double mean = g_sum / nd;
    double var = (g_sumsq - nd * mean * mean) / (nd - 1.0);
    double sf = sqrt(var) / mean;
    sf = fmin(fmax(sf, 0.5), 2.0);
    for (int i = 0; i < NS; i++) {
        double v = exp((double)scale_params[i]) * sf;
        v = fmin(fmax(v, 2.0), 16.0);
        int s = (int)v;                 // trunc == python int() for positive
        g_scales[i] = s;
        g_s2[i] = (float)(s * s);
        int n = (DIM / s) * s;
        double ps = 0.0;
        for (int j = 0; j < n; j++) ps += g_colsum[j];
        g_boxthr[i] = (float)(ps / ((double)N_PTS * (double)n));
    }
    float mn = mono2f(g_minbits), mx = mono2f(g_maxbits);
    g_hmin = mn; g_hrange = mx - mn;
}

// ---------------- K3: box counting (avg-pool then count > mean) ----------------
__global__ void k_box(const float* __restrict__ x) {
    __shared__ float sr[8][DIM];
    int t = threadIdx.x;
    int si = blockIdx.y;
    int base = blockIdx.x * 8 * DIM;
    for (int i = t; i < 8 * DIM; i += 256) ((float*)sr)[i] = x[base + i];
    __syncthreads();
    int w = t >> 5, lane = t & 31;
    int s = g_scales[si];
    float thr = g_boxthr[si];
    int m = DIM / s;
    float inv = 1.0f / (float)s;
    int cnt = 0;
    for (int g = lane; g < m; g += 32) {
        float sum = 0.f;
        for (int k = 0; k < s; k++) sum += sr[w][g * s + k];
        cnt += (sum * inv > thr);
    }
    for (int o = 16; o; o >>= 1) cnt += __shfl_down_sync(0xffffffffu, cnt, o);
    if (!lane) atomicAdd(&g_box_cnt[si], (unsigned long long)cnt);
}

// ---------------- K4: histograms via warp-ballot counting ----------------
__global__ void k_hist(const float* __restrict__ x) {
    int lane = threadIdx.x & 31;
    unsigned cnt[NS];
#pragma unroll
    for (int i = 0; i < NS; i++) cnt[i] = 0;
    float mn = g_hmin, rng = g_hrange;
    float invr = rng > 0.f ? 1.0f / rng : 0.f;
    int scl[NS]; float fs[NS];
#pragma unroll
    for (int i = 0; i < NS; i++) { scl[i] = g_scales[i]; fs[i] = (float)scl[i]; }
    for (int idx = blockIdx.x * blockDim.x + threadIdx.x; idx < N_PTS * DIM;
         idx += gridDim.x * blockDim.x) {
        float u = (x[idx] - mn) * invr;
#pragma unroll
        for (int i = 0; i < NS; i++) {
            int b = (int)(u * fs[i]);
            b = min(b, scl[i] - 1); b = max(b, 0);
            for (int bb = 0; bb < scl[i]; bb++) {
                unsigned m = __ballot_sync(0xffffffffu, b == bb);
                if (lane == bb) cnt[i] += __popc(m);
            }
        }
    }
#pragma unroll
    for (int i = 0; i < NS; i++)
        if (lane < scl[i] && cnt[i]) atomicAdd(&g_hist[i][lane], (unsigned long long)cnt[i]);
}

// ---------------- K5: pairwise distance threshold counts (the hot kernel) ----------------
// Symmetric: only lower-triangular tile grid; off-diagonal tiles count x2.
__global__ void __launch_bounds__(256, 2) k_corr(const float* __restrict__ x) {
    // decode linear block -> (r,c) with c<=r
    int kblk = blockIdx.x;
    int r = (int)((sqrtf(8.0f * (float)kblk + 1.0f) - 1.0f) * 0.5f);
    while ((r + 1) * (r + 2) / 2 <= kblk) r++;
    while (r * (r + 1) / 2 > kblk) r--;
    int c = kblk - r * (r + 1) / 2;
    int bx = r, by = c;                       // bx >= by
    int mult = (bx == by) ? 1 : 2;

    const float* Arows = x + by * BM * DIM;
    const float* Brows = x + bx * BM * DIM;

    __shared__ float As[BK][BM + 4];
    __shared__ float Bs[BK][BM + 4];

    int tid = threadIdx.x;
    int tx = tid & 15, ty = tid >> 4;

    float acc[8][8];
#pragma unroll
    for (int i = 0; i < 8; i++)
#pragma unroll
        for (int j = 0; j < 8; j++) acc[i][j] = 0.f;

    for (int kk = 0; kk < DIM; kk += BK) {
#pragma unroll
        for (int l = 0; l < 2; l++) {
            int idx = tid + l * 256;          // 0..511
            int row = idx >> 2;
            int kq  = (idx & 3) * 4;
            float4 va = *(const float4*)(Arows + row * DIM + kk + kq);
            As[kq + 0][row] = va.x; As[kq + 1][row] = va.y;
            As[kq + 2][row] = va.z; As[kq + 3][row] = va.w;
            float4 vb = *(const float4*)(Brows + row * DIM + kk + kq);
            Bs[kq + 0][row] = vb.x; Bs[kq + 1][row] = vb.y;
            Bs[kq + 2][row] = vb.z; Bs[kq + 3][row] = vb.w;
        }
        __syncthreads();
#pragma unroll
        for (int p = 0; p < BK; p++) {
            float a[8], b[8];
#pragma unroll
            for (int i = 0; i < 8; i++) a[i] = As[p][ty * 8 + i];
#pragma unroll
            for (int j = 0; j < 8; j++) b[j] = Bs[p][tx * 8 + j];
#pragma unroll
            for (int i = 0; i < 8; i++)
#pragma unroll
                for (int j = 0; j < 8; j++) acc[i][j] += a[i] * b[j];
        }
        __syncthreads();
    }

    float sqa[8], sqb[8];
#pragma unroll
    for (int i = 0; i < 8; i++) {
        sqa[i] = g_rowsq[by * BM + ty * 8 + i];
        sqb[i] = g_rowsq[bx * BM + tx * 8 + i];
    }
    float s2[NS];
#pragma unroll
    for (int q = 0; q < NS; q++) s2[q] = g_s2[q];
    int cnt[NS];
#pragma unroll
    for (int q = 0; q < NS; q++) cnt[q] = 0;
#pragma unroll
    for (int i = 0; i < 8; i++)
#pragma unroll
        for (int j = 0; j < 8; j++) {
            float d2 = sqa[i] + sqb[j] - 2.0f * acc[i][j];
#pragma unroll
            for (int q = 0; q < NS; q++) cnt[q] += (d2 < s2[q]);
        }

    __shared__ int scnt[NS];
    if (tid < NS) scnt[tid] = 0;
    __syncthreads();
#pragma unroll
    for (int q = 0; q < NS; q++) {
        int v = cnt[q];
        for (int o = 16; o; o >>= 1) v += __shfl_down_sync(0xffffffffu, v, o);
        if ((tid & 31) == 0) atomicAdd(&scnt[q], v);
    }
    __syncthreads();
    if (tid < NS)
        atomicAdd(&g_corr_cnt[tid], (unsigned long long)((long long)scnt[tid] * mult));
}

// ---------------- K6: slopes + softmax-weighted output (1 thread) ----------------
__device__ double dslope(const double* xv, const double* yv, int n) {
    double xm = 0, ym = 0;
    for (int i = 0; i < n; i++) { xm += xv[i]; ym += yv[i]; }
    xm /= n; ym /= n;
    double num = 0, den = 0;
    for (int i = 0; i < n; i++) {
        double dx = xv[i] - xm;
        num += dx * (yv[i] - ym);
        den += dx * dx;
    }
    return num / den;
}

__global__ void k_final(const float* __restrict__ simp, float* __restrict__ out) {
    double logs[NS], yb[NS], yc[NS], yi[NS];
    for (int i = 0; i < NS; i++) {
        logs[i] = log((double)(float)g_scales[i]);
        yb[i] = log((double)g_box_cnt[i]);
        yc[i] = log((double)g_corr_cnt[i]);
        unsigned long long tot = 0;
        for (int b = 0; b < g_scales[i]; b++) tot += g_hist[i][b];
        double ent = 0.0;
        for (int b = 0; b < g_scales[i]; b++) {
            if (g_hist[i][b] > 0) {
                double p = (double)g_hist[i][b] / (double)tot;
                ent -= p * log(p);
            }
        }
        yi[i] = ent;
    }
    double box_dim  = -dslope(logs, yb, NS);
    double corr_dim =  dslope(logs, yc, NS);
    double info_dim =  dslope(logs, yi, NS);

    float mx = simp[0];
    for (int i = 1; i < NS; i++) mx = fmaxf(mx, simp[i]);
    double w[NS], den = 0.0;
    for (int i = 0; i < NS; i++) { w[i] = exp((double)(simp[i] - mx)); den += w[i]; }
    double o = (w[0] * box_dim + w[1] * corr_dim + w[2] * info_dim) / den;
    out[0] = (float)o;
}

// ---------------- launch ----------------
extern "C" void kernel_launch(void* const* d_in, const int* in_sizes, int n_in,
                              void* d_out, int out_size) {
    const float* x    = (const float*)d_in[0];
    const float* sp   = (const float*)d_in[1];
    const float* simp = (const float*)d_in[2];
    float* out = (float*)d_out;

    k_init<<<1, 256>>>();
    k_stats<<<512, 256>>>(x);
    k_rowsq<<<(N_PTS * 32) / 256, 256>>>(x);
    k_setup<<<1, 1>>>(sp);
    k_box<<<dim3(N_PTS / 8, NS), 256>>>(x);
    k_hist<<<296, 256>>>(x);
    int ntiles = N_PTS / BM;                   // 64
    k_corr<<<ntiles * (ntiles + 1) / 2, 256>>>(x);
    k_final<<<1, 1>>>(simp, out);
}

// round 4
// speedup vs baseline: 2.7922x; 2.7922x over previous
#include <cuda_runtime.h>
#include <cuda_bf16.h>
#include <math.h>
#include <stdint.h>

constexpr int kN   = 8192;   // points
constexpr int kD   = 256;    // dim
constexpr int kNS  = 5;      // scales
constexpr int kBM  = 128;    // block tile (M and N)
constexpr int kBK  = 32;     // k tile
constexpr int kLds = 40;     // smem row stride in bf16 elems (32 + 8 pad)

// ---------------- device scratch (no allocations allowed) ----------------
__device__ double g_sum;
__device__ double g_sumsq;
__device__ double g_colsum[kD];
__device__ unsigned int g_minbits;
__device__ unsigned int g_maxbits;
__device__ float  g_rowsq[kN];
__device__ __nv_bfloat16 g_xb[kN * kD];
__device__ int    g_scales[kNS];
__device__ float  g_s2[kNS];
__device__ float  g_boxthr[kNS];
__device__ float  g_hmin;
__device__ float  g_hrange;
__device__ unsigned long long g_box_cnt[kNS];
__device__ unsigned long long g_corr_cnt[kNS];
__device__ unsigned long long g_hist[kNS][16];

__device__ __forceinline__ unsigned f2mono(float f) {
    unsigned u = __float_as_uint(f);
    return (u & 0x80000000u) ? ~u : (u | 0x80000000u);
}
__device__ __forceinline__ float mono2f(unsigned u) {
    unsigned b = (u & 0x80000000u) ? (u & 0x7fffffffu) : ~u;
    return __uint_as_float(b);
}

// ---------------- K0: zero scratch (graph replays => must re-init) ----------------
__global__ void k_init() {
    int t = threadIdx.x;
    if (t == 0) {
        g_sum = 0.0;
        g_sumsq = 0.0;
        g_minbits = 0xFFFFFFFFu;
        g_maxbits = 0u;
    }
    if (t < kD) {
        g_colsum[t] = 0.0;
    }
    if (t < kNS) {
        g_box_cnt[t] = 0ull;
        g_corr_cnt[t] = 0ull;
    }
    if (t < kNS * 16) {
        ((unsigned long long*)g_hist)[t] = 0ull;
    }
}

// ---------------- K1: global sum/sumsq/min/max + per-column sums ----------------
__global__ void k_stats(const float* __restrict__ x) {
    __shared__ double s_sum[256];
    __shared__ double s_sq[256];
    __shared__ unsigned s_min[256];
    __shared__ unsigned s_max[256];
    int t = threadIdx.x;
    double ls = 0.0;
    double lq = 0.0;
    double lcol = 0.0;
    unsigned lmin = 0xFFFFFFFFu;
    unsigned lmax = 0u;
    for (int i = blockIdx.x * 256 + t; i < kN * kD; i += gridDim.x * 256) {
        float v = x[i];
        ls += v;
        lq += (double)v * (double)v;
        lcol += v;
        unsigned m = f2mono(v);
        lmin = min(lmin, m);
        lmax = max(lmax, m);
    }
    atomicAdd(&g_colsum[t], lcol);
    s_sum[t] = ls;
    s_sq[t] = lq;
    s_min[t] = lmin;
    s_max[t] = lmax;
    __syncthreads();
    for (int o = 128; o > 0; o >>= 1) {
        if (t < o) {
            s_sum[t] += s_sum[t + o];
            s_sq[t] += s_sq[t + o];
            s_min[t] = min(s_min[t], s_min[t + o]);
            s_max[t] = max(s_max[t], s_max[t + o]);
        }
        __syncthreads();
    }
    if (t == 0) {
        atomicAdd(&g_sum, s_sum[0]);
        atomicAdd(&g_sumsq, s_sq[0]);
        atomicMin(&g_minbits, s_min[0]);
        atomicMax(&g_maxbits, s_max[0]);
    }
}

// ---------------- K1b: bf16 conversion + per-row squared norms (fused) ----------------
__global__ void k_cvt(const float* __restrict__ x) {
    int w = threadIdx.x >> 5;
    int lane = threadIdx.x & 31;
    int row = blockIdx.x * 8 + w;
    const float4* xr = (const float4*)(x + row * kD);
    float4 a = xr[lane];
    float4 b = xr[lane + 32];
    float s = a.x * a.x + a.y * a.y + a.z * a.z + a.w * a.w
            + b.x * b.x + b.y * b.y + b.z * b.z + b.w * b.w;
    for (int o = 16; o > 0; o >>= 1) {
        s += __shfl_down_sync(0xffffffffu, s, o);
    }
    if (lane == 0) {
        g_rowsq[row] = s;
    }
    __nv_bfloat162* dst = (__nv_bfloat162*)(g_xb + row * kD);
    dst[lane * 2 + 0] = __floats2bfloat162_rn(a.x, a.y);
    dst[lane * 2 + 1] = __floats2bfloat162_rn(a.z, a.w);
    dst[64 + lane * 2 + 0] = __floats2bfloat162_rn(b.x, b.y);
    dst[64 + lane * 2 + 1] = __floats2bfloat162_rn(b.z, b.w);
}

// ---------------- K2: scales + thresholds (parallel, 1 block) ----------------
__global__ void k_setup(const float* __restrict__ scale_params) {
    __shared__ double scol[256];
    __shared__ double red[256];
    __shared__ int ssc[kNS];
    int t = threadIdx.x;
    scol[t] = g_colsum[t];
    if (t == 0) {
        double nd = (double)kN * (double)kD;
        double mean = g_sum / nd;
        double var = (g_sumsq - nd * mean * mean) / (nd - 1.0);
        double sf = sqrt(var) / mean;
        sf = fmin(fmax(sf, 0.5), 2.0);
        for (int i = 0; i < kNS; i++) {
            double v = exp((double)scale_params[i]) * sf;
            v = fmin(fmax(v, 2.0), 16.0);
            int si = (int)v;
            g_scales[i] = si;
            ssc[i] = si;
            g_s2[i] = (float)(si * si);
        }
        float mn = mono2f(g_minbits);
        float mx = mono2f(g_maxbits);
        g_hmin = mn;
        g_hrange = mx - mn;
    }
    __syncthreads();
    for (int i = 0; i < kNS; i++) {
        int n = (kD / ssc[i]) * ssc[i];
        red[t] = (t < n) ? scol[t] : 0.0;
        __syncthreads();
        for (int o = 128; o > 0; o >>= 1) {
            if (t < o) {
                red[t] += red[t + o];
            }
            __syncthreads();
        }
        if (t == 0) {
            g_boxthr[i] = (float)(red[0] / ((double)kN * (double)n));
        }
        __syncthreads();
    }
}

// ---------------- K3: box counting ----------------
__global__ void k_box(const float* __restrict__ x) {
    __shared__ float sr[8][kD];
    int t = threadIdx.x;
    int si = blockIdx.y;
    int base = blockIdx.x * 8 * kD;
    for (int i = t; i < 8 * kD; i += 256) {
        ((float*)sr)[i] = x[base + i];
    }
    __syncthreads();
    int w = t >> 5;
    int lane = t & 31;
    int s = g_scales[si];
    float thr = g_boxthr[si];
    int m = kD / s;
    float inv = 1.0f / (float)s;
    int cnt = 0;
    for (int g = lane; g < m; g += 32) {
        float sum = 0.f;
        for (int k = 0; k < s; k++) {
            sum += sr[w][g * s + k];
        }
        cnt += (sum * inv > thr) ? 1 : 0;
    }
    for (int o = 16; o > 0; o >>= 1) {
        cnt += __shfl_down_sync(0xffffffffu, cnt, o);
    }
    if (lane == 0) {
        atomicAdd(&g_box_cnt[si], (unsigned long long)cnt);
    }
}

// ---------------- K4: histograms via warp-ballot counting ----------------
__global__ void k_hist(const float* __restrict__ x) {
    int lane = threadIdx.x & 31;
    unsigned cnt[kNS];
    for (int i = 0; i < kNS; i++) {
        cnt[i] = 0;
    }
    float mn = g_hmin;
    float rng = g_hrange;
    float invr = (rng > 0.f) ? (1.0f / rng) : 0.f;
    int scl[kNS];
    float fs[kNS];
    for (int i = 0; i < kNS; i++) {
        scl[i] = g_scales[i];
        fs[i] = (float)scl[i];
    }
    for (int idx = blockIdx.x * blockDim.x + threadIdx.x; idx < kN * kD;
         idx += gridDim.x * blockDim.x) {
        float u = (x[idx] - mn) * invr;
        for (int i = 0; i < kNS; i++) {
            int b = (int)(u * fs[i]);
            b = min(b, scl[i] - 1);
            b = max(b, 0);
            for (int bb = 0; bb < scl[i]; bb++) {
                unsigned m = __ballot_sync(0xffffffffu, b == bb);
                if (lane == bb) {
                    cnt[i] += __popc(m);
                }
            }
        }
    }
    for (int i = 0; i < kNS; i++) {
        if (lane < scl[i] && cnt[i] != 0) {
            atomicAdd(&g_hist[i][lane], (unsigned long long)cnt[i]);
        }
    }
}

// ---------------- K5: pairwise distance counts via bf16 tensor cores ----------------
__device__ __forceinline__ void ldmat_x4(uint32_t& r0, uint32_t& r1,
                                         uint32_t& r2, uint32_t& r3,
                                         const __nv_bfloat16* p) {
    uint32_t addr = (uint32_t)__cvta_generic_to_shared(p);
    asm volatile(
        "ldmatrix.sync.aligned.m8n8.x4.shared.b16 {%0,%1,%2,%3}, [%4];"
        : "=r"(r0), "=r"(r1), "=r"(r2), "=r"(r3)
        : "r"(addr));
}

__device__ __forceinline__ void mma_bf16(float* c, const uint32_t* a,
                                         uint32_t b0, uint32_t b1) {
    asm volatile(
        "mma.sync.aligned.m16n8k16.row.col.f32.bf16.bf16.f32 "
        "{%0,%1,%2,%3}, {%4,%5,%6,%7}, {%8,%9}, {%0,%1,%2,%3};"
        : "+f"(c[0]), "+f"(c[1]), "+f"(c[2]), "+f"(c[3])
        : "r"(a[0]), "r"(a[1]), "r"(a[2]), "r"(a[3]), "r"(b0), "r"(b1));
}

__global__ void __launch_bounds__(256, 2) k_corr() {
    int kblk = blockIdx.x;
    int r = (int)((sqrtf(8.0f * (float)kblk + 1.0f) - 1.0f) * 0.5f);
    while ((r + 1) * (r + 2) / 2 <= kblk) {
        r++;
    }
    while (r * (r + 1) / 2 > kblk) {
        r--;
    }
    int c = kblk - r * (r + 1) / 2;
    int bx = r;
    int by = c;
    int mult = (bx == by) ? 1 : 2;

    const __nv_bfloat16* Arows = g_xb + by * kBM * kD;
    const __nv_bfloat16* Brows = g_xb + bx * kBM * kD;

    __shared__ __align__(16) __nv_bfloat16 As[kBM][kLds];
    __shared__ __align__(16) __nv_bfloat16 Bs[kBM][kLds];

    int tid = threadIdx.x;
    int lane = tid & 31;
    int wid = tid >> 5;
    int warpM = wid & 3;
    int warpN = wid >> 2;
    int m0 = warpM * 32;
    int n0 = warpN * 64;

    float acc[2][8][4];
    for (int i = 0; i < 2; i++) {
        for (int j = 0; j < 8; j++) {
            for (int q = 0; q < 4; q++) {
                acc[i][j][q] = 0.f;
            }
        }
    }

    for (int kk = 0; kk < kD; kk += kBK) {
        // stage 128x32 bf16 of A and B: 512 uint4 each, 2 per thread
        for (int l = 0; l < 2; l++) {
            int idx = tid + l * 256;      // 0..511
            int row = idx >> 2;           // 0..127
            int q = idx & 3;              // 0..3 -> columns q*8 .. q*8+7
            *(uint4*)(&As[row][q * 8]) = *(const uint4*)(Arows + row * kD + kk + q * 8);
            *(uint4*)(&Bs[row][q * 8]) = *(const uint4*)(Brows + row * kD + kk + q * 8);
        }
        __syncthreads();
        for (int k16 = 0; k16 < kBK; k16 += 16) {
            uint32_t afr[2][4];
            for (int mi = 0; mi < 2; mi++) {
                const __nv_bfloat16* pa =
                    &As[m0 + mi * 16 + (lane & 15)][k16 + ((lane >> 4) & 1) * 8];
                ldmat_x4(afr[mi][0], afr[mi][1], afr[mi][2], afr[mi][3], pa);
            }
            uint32_t bfr[4][4];
            int quad = lane >> 3;
            int l7 = lane & 7;
            for (int g = 0; g < 4; g++) {
                const __nv_bfloat16* pb =
                    &Bs[n0 + g * 16 + ((quad >> 1) & 1) * 8 + l7][k16 + (quad & 1) * 8];
                ldmat_x4(bfr[g][0], bfr[g][1], bfr[g][2], bfr[g][3], pb);
            }
            for (int mi = 0; mi < 2; mi++) {
                for (int nt = 0; nt < 8; nt++) {
                    int g = nt >> 1;
                    int ph = nt & 1;
                    mma_bf16(acc[mi][nt], afr[mi], bfr[g][ph * 2], bfr[g][ph * 2 + 1]);
                }
            }
        }
        __syncthreads();
    }

    float sqa[2][2];
    for (int mi = 0; mi < 2; mi++) {
        for (int h = 0; h < 2; h++) {
            sqa[mi][h] = g_rowsq[by * kBM + m0 + mi * 16 + (lane >> 2) + h * 8];
        }
    }
    float sqb[8][2];
    for (int nt = 0; nt < 8; nt++) {
        for (int j = 0; j < 2; j++) {
            sqb[nt][j] = g_rowsq[bx * kBM + n0 + nt * 8 + 2 * (lane & 3) + j];
        }
    }

    float s2[kNS];
    for (int q = 0; q < kNS; q++) {
        s2[q] = g_s2[q];
    }
    int cnt[kNS];
    for (int q = 0; q < kNS; q++) {
        cnt[q] = 0;
    }
    for (int mi = 0; mi < 2; mi++) {
        for (int nt = 0; nt < 8; nt++) {
            for (int q4 = 0; q4 < 4; q4++) {
                int h = q4 >> 1;
                int j = q4 & 1;
                float d2 = sqa[mi][h] + sqb[nt][j] - 2.0f * acc[mi][nt][q4];
                for (int q = 0; q < kNS; q++) {
                    cnt[q] += (d2 < s2[q]) ? 1 : 0;
                }
            }
        }
    }

    __shared__ int scnt[kNS];
    if (tid < kNS) {
        scnt[tid] = 0;
    }
    __syncthreads();
    for (int q = 0; q < kNS; q++) {
        int v = cnt[q];
        for (int o = 16; o > 0; o >>= 1) {
            v += __shfl_down_sync(0xffffffffu, v, o);
        }
        if (lane == 0) {
            atomicAdd(&scnt[q], v);
        }
    }
    __syncthreads();
    if (tid < kNS) {
        long long total = (long long)scnt[tid] * (long long)mult;
        atomicAdd(&g_corr_cnt[tid], (unsigned long long)total);
    }
}

// ---------------- K6: slopes + softmax-weighted output (1 thread) ----------------
__device__ double dslope(const double* xv, const double* yv, int n) {
    double xm = 0.0;
    double ym = 0.0;
    for (int i = 0; i < n; i++) {
        xm += xv[i];
        ym += yv[i];
    }
    xm /= n;
    ym /= n;
    double num = 0.0;
    double den = 0.0;
    for (int i = 0; i < n; i++) {
        double dx = xv[i] - xm;
        num += dx * (yv[i] - ym);
        den += dx * dx;
    }
    return num / den;
}

__global__ void k_final(const float* __restrict__ simp, float* __restrict__ outp) {
    double logs[kNS];
    double yb[kNS];
    double yc[kNS];
    double yi[kNS];
    for (int i = 0; i < kNS; i++) {
        logs[i] = log((double)(float)g_scales[i]);
        yb[i] = log((double)g_box_cnt[i]);
        yc[i] = log((double)g_corr_cnt[i]);
        unsigned long long tot = 0;
        for (int b = 0; b < g_scales[i]; b++) {
            tot += g_hist[i][b];
        }
        double ent = 0.0;
        for (int b = 0; b < g_scales[i]; b++) {
            if (g_hist[i][b] > 0) {
                double p = (double)g_hist[i][b] / (double)tot;
                ent -= p * log(p);
            }
        }
        yi[i] = ent;
    }
    double box_dim = -dslope(logs, yb, kNS);
    double corr_dim = dslope(logs, yc, kNS);
    double info_dim = dslope(logs, yi, kNS);

    float mx = simp[0];
    for (int i = 1; i < kNS; i++) {
        mx = fmaxf(mx, simp[i]);
    }
    double w[kNS];
    double den = 0.0;
    for (int i = 0; i < kNS; i++) {
        w[i] = exp((double)(simp[i] - mx));
        den += w[i];
    }
    double o = (w[0] * box_dim + w[1] * corr_dim + w[2] * info_dim) / den;
    outp[0] = (float)o;
}

// ---------------- launch ----------------
extern "C" void kernel_launch(void* const* d_in, const int* in_sizes, int n_in,
                              void* d_out, int out_size) {
    const float* x = (const float*)d_in[0];
    const float* sp = (const float*)d_in[1];
    const float* simp = (const float*)d_in[2];
    float* outp = (float*)d_out;

    k_init<<<1, 256>>>();
    k_stats<<<512, 256>>>(x);
    k_cvt<<<kN / 8, 256>>>(x);
    k_setup<<<1, 256>>>(sp);
    k_box<<<dim3(kN / 8, kNS), 256>>>(x);
    k_hist<<<296, 256>>>(x);
    int ntiles = kN / kBM;
    k_corr<<<ntiles * (ntiles + 1) / 2, 256>>>();
    k_final<<<1, 1>>>(simp, outp);
}

// round 5
// speedup vs baseline: 3.5930x; 1.2868x over previous
#include <cuda_runtime.h>
#include <cuda_bf16.h>
#include <math.h>
#include <stdint.h>

constexpr int kN   = 8192;   // points
constexpr int kD   = 256;    // dim
constexpr int kNS  = 5;      // scales
constexpr int kBM  = 128;    // block tile (M and N)
constexpr int kBK  = 32;     // k tile
constexpr int kLds = 40;     // smem row stride in bf16 elems (32 + 8 pad)

// ---------------- device scratch (no allocations allowed) ----------------
__device__ double g_sumsq;
__device__ double g_colsum[kD];
__device__ unsigned int g_minbits;
__device__ unsigned int g_maxbits;
__device__ float  g_rowsq[kN];
__device__ __nv_bfloat16 g_xb[kN * kD];
__device__ int    g_scales[kNS];
__device__ float  g_s2[kNS];
__device__ float  g_boxthr[kNS];
__device__ float  g_hmin;
__device__ float  g_hrange;
__device__ unsigned long long g_box_cnt[kNS];
__device__ unsigned long long g_corr_cnt[kNS];
__device__ unsigned long long g_hist[kNS][16];

__device__ __forceinline__ unsigned f2mono(float f) {
    unsigned u = __float_as_uint(f);
    return (u & 0x80000000u) ? ~u : (u | 0x80000000u);
}
__device__ __forceinline__ float mono2f(unsigned u) {
    unsigned b = (u & 0x80000000u) ? (u & 0x7fffffffu) : ~u;
    return __uint_as_float(b);
}

// ---------------- K0: zero scratch (graph replays => must re-init) ----------------
__global__ void k_init() {
    int t = threadIdx.x;
    if (t == 0) {
        g_sumsq = 0.0;
        g_minbits = 0xFFFFFFFFu;
        g_maxbits = 0u;
    }
    if (t < kD) {
        g_colsum[t] = 0.0;
    }
    if (t < kNS) {
        g_box_cnt[t] = 0ull;
        g_corr_cnt[t] = 0ull;
    }
    if (t < kNS * 16) {
        ((unsigned long long*)g_hist)[t] = 0ull;
    }
}

// ---------------- K1: fused stats + bf16 conversion + row norms ----------------
// 8 warps per block, one row per warp.
__global__ void k_statscvt(const float* __restrict__ x) {
    __shared__ double scol[kD];
    __shared__ double ssq[256];
    __shared__ unsigned smin[256];
    __shared__ unsigned smax[256];
    int t = threadIdx.x;
    int w = t >> 5;
    int lane = t & 31;
    int row = blockIdx.x * 8 + w;

    scol[t] = 0.0;
    __syncthreads();

    const float4* xr = (const float4*)(x + row * kD);
    float4 a = xr[lane];
    float4 b = xr[lane + 32];

    // row squared norm
    float s = a.x * a.x + a.y * a.y + a.z * a.z + a.w * a.w
            + b.x * b.x + b.y * b.y + b.z * b.z + b.w * b.w;
    for (int o = 16; o > 0; o >>= 1) {
        s += __shfl_down_sync(0xffffffffu, s, o);
    }
    if (lane == 0) {
        g_rowsq[row] = s;
    }

    // bf16 store
    __nv_bfloat162* dst = (__nv_bfloat162*)(g_xb + row * kD);
    dst[lane * 2 + 0] = __floats2bfloat162_rn(a.x, a.y);
    dst[lane * 2 + 1] = __floats2bfloat162_rn(a.z, a.w);
    dst[64 + lane * 2 + 0] = __floats2bfloat162_rn(b.x, b.y);
    dst[64 + lane * 2 + 1] = __floats2bfloat162_rn(b.z, b.w);

    // column sums (conflict degree 8 across warps)
    atomicAdd(&scol[lane * 4 + 0], (double)a.x);
    atomicAdd(&scol[lane * 4 + 1], (double)a.y);
    atomicAdd(&scol[lane * 4 + 2], (double)a.z);
    atomicAdd(&scol[lane * 4 + 3], (double)a.w);
    atomicAdd(&scol[128 + lane * 4 + 0], (double)b.x);
    atomicAdd(&scol[128 + lane * 4 + 1], (double)b.y);
    atomicAdd(&scol[128 + lane * 4 + 2], (double)b.z);
    atomicAdd(&scol[128 + lane * 4 + 3], (double)b.w);

    // sumsq / min / max block reduction
    double lq = (double)a.x * a.x + (double)a.y * a.y + (double)a.z * a.z + (double)a.w * a.w
              + (double)b.x * b.x + (double)b.y * b.y + (double)b.z * b.z + (double)b.w * b.w;
    unsigned lmin = min(min(min(f2mono(a.x), f2mono(a.y)), min(f2mono(a.z), f2mono(a.w))),
                        min(min(f2mono(b.x), f2mono(b.y)), min(f2mono(b.z), f2mono(b.w))));
    unsigned lmax = max(max(max(f2mono(a.x), f2mono(a.y)), max(f2mono(a.z), f2mono(a.w))),
                        max(max(f2mono(b.x), f2mono(b.y)), max(f2mono(b.z), f2mono(b.w))));
    ssq[t] = lq;
    smin[t] = lmin;
    smax[t] = lmax;
    __syncthreads();
    for (int o = 128; o > 0; o >>= 1) {
        if (t < o) {
            ssq[t] += ssq[t + o];
            smin[t] = min(smin[t], smin[t + o]);
            smax[t] = max(smax[t], smax[t + o]);
        }
        __syncthreads();
    }
    if (t == 0) {
        atomicAdd(&g_sumsq, ssq[0]);
        atomicMin(&g_minbits, smin[0]);
        atomicMax(&g_maxbits, smax[0]);
    }
    atomicAdd(&g_colsum[t], scol[t]);
}

// ---------------- K2: scales + thresholds (single warp) ----------------
__global__ void k_setup(const float* __restrict__ scale_params) {
    int lane = threadIdx.x;

    // total sum from column sums
    double p = g_colsum[lane] + g_colsum[lane + 32] + g_colsum[lane + 64] + g_colsum[lane + 96]
             + g_colsum[lane + 128] + g_colsum[lane + 160] + g_colsum[lane + 192] + g_colsum[lane + 224];
    for (int o = 16; o > 0; o >>= 1) {
        p += __shfl_down_sync(0xffffffffu, p, o);
    }
    double tot = __shfl_sync(0xffffffffu, p, 0);

    int scl = 0;
    if (lane < kNS) {
        double nd = (double)kN * (double)kD;
        double mean = tot / nd;
        double var = (g_sumsq - nd * mean * mean) / (nd - 1.0);
        double sf = sqrt(var) / mean;
        sf = fmin(fmax(sf, 0.5), 2.0);
        double v = exp((double)scale_params[lane]) * sf;
        v = fmin(fmax(v, 2.0), 16.0);
        scl = (int)v;
        g_scales[lane] = scl;
        g_s2[lane] = (float)(scl * scl);
    }
    if (lane == 0) {
        float mn = mono2f(g_minbits);
        float mx = mono2f(g_maxbits);
        g_hmin = mn;
        g_hrange = mx - mn;
    }

    for (int i = 0; i < kNS; i++) {
        int s = __shfl_sync(0xffffffffu, scl, i);
        int n = (kD / s) * s;
        double q = 0.0;
        for (int j = lane; j < n; j += 32) {
            q += g_colsum[j];
        }
        for (int o = 16; o > 0; o >>= 1) {
            q += __shfl_down_sync(0xffffffffu, q, o);
        }
        if (lane == 0) {
            g_boxthr[i] = (float)(q / ((double)kN * (double)n));
        }
    }
}

// ---------------- K3: fused box counting + histograms (one pass over x) ----------------
__global__ void k_boxhist(const float* __restrict__ x) {
    __shared__ float sr[8][kD];
    __shared__ int sh[kNS][16];
    __shared__ int sbox[kNS];
    __shared__ float sthr[kNS];
    __shared__ int sscl[kNS];
    int t = threadIdx.x;
    int base = blockIdx.x * 8 * kD;
    for (int i = t; i < 8 * kD; i += 256) {
        ((float*)sr)[i] = x[base + i];
    }
    if (t < kNS * 16) {
        ((int*)sh)[t] = 0;
    }
    if (t < kNS) {
        sbox[t] = 0;
        sthr[t] = g_boxthr[t];
        sscl[t] = g_scales[t];
    }
    __syncthreads();

    int w = t >> 5;
    int lane = t & 31;

    // box counting: warp w handles row w, all scales
    for (int si = 0; si < kNS; si++) {
        int s = sscl[si];
        float thr = sthr[si];
        int m = kD / s;
        float inv = 1.0f / (float)s;
        int cnt = 0;
        for (int g = lane; g < m; g += 32) {
            float sum = 0.f;
            for (int k = 0; k < s; k++) {
                sum += sr[w][g * s + k];
            }
            cnt += (sum * inv > thr) ? 1 : 0;
        }
        for (int o = 16; o > 0; o >>= 1) {
            cnt += __shfl_down_sync(0xffffffffu, cnt, o);
        }
        if (lane == 0) {
            atomicAdd(&sbox[si], cnt);
        }
    }

    // histograms via match_any: each thread processes 8 elements
    float mn = g_hmin;
    float rng = g_hrange;
    float invr = (rng > 0.f) ? (1.0f / rng) : 0.f;
    for (int i = 0; i < 8; i++) {
        float v = ((const float*)sr)[t + i * 256];
        float u = (v - mn) * invr;
        for (int si = 0; si < kNS; si++) {
            int s = sscl[si];
            int b = (int)(u * (float)s);
            b = min(b, s - 1);
            b = max(b, 0);
            unsigned msk = __match_any_sync(0xffffffffu, b);
            int leader = __ffs(msk) - 1;
            if (lane == leader) {
                atomicAdd(&sh[si][b], __popc(msk));
            }
        }
    }
    __syncthreads();
    if (t < kNS) {
        atomicAdd(&g_box_cnt[t], (unsigned long long)sbox[t]);
    }
    if (t < kNS * 16) {
        int v = ((int*)sh)[t];
        if (v != 0) {
            atomicAdd(&((unsigned long long*)g_hist)[t], (unsigned long long)v);
        }
    }
}

// ---------------- K5: pairwise distance counts via bf16 tensor cores ----------------
__device__ __forceinline__ void ldmat_x4(uint32_t& r0, uint32_t& r1,
                                         uint32_t& r2, uint32_t& r3,
                                         const __nv_bfloat16* p) {
    uint32_t addr = (uint32_t)__cvta_generic_to_shared(p);
    asm volatile(
        "ldmatrix.sync.aligned.m8n8.x4.shared.b16 {%0,%1,%2,%3}, [%4];"
        : "=r"(r0), "=r"(r1), "=r"(r2), "=r"(r3)
        : "r"(addr));
}

__device__ __forceinline__ void mma_bf16(float* c, const uint32_t* a,
                                         uint32_t b0, uint32_t b1) {
    asm volatile(
        "mma.sync.aligned.m16n8k16.row.col.f32.bf16.bf16.f32 "
        "{%0,%1,%2,%3}, {%4,%5,%6,%7}, {%8,%9}, {%0,%1,%2,%3};"
        : "+f"(c[0]), "+f"(c[1]), "+f"(c[2]), "+f"(c[3])
        : "r"(a[0]), "r"(a[1]), "r"(a[2]), "r"(a[3]), "r"(b0), "r"(b1));
}

__device__ __forceinline__ void cp16(void* sp, const void* gp) {
    uint32_t a = (uint32_t)__cvta_generic_to_shared(sp);
    asm volatile("cp.async.ca.shared.global [%0], [%1], 16;" :: "r"(a), "l"(gp));
}
__device__ __forceinline__ void cp_commit() {
    asm volatile("cp.async.commit_group;");
}
template <int n>
__device__ __forceinline__ void cp_wait() {
    asm volatile("cp.async.wait_group %0;" :: "n"(n));
}

__global__ void __launch_bounds__(256, 2) k_corr() {
    int kblk = blockIdx.x;
    int r = (int)((sqrtf(8.0f * (float)kblk + 1.0f) - 1.0f) * 0.5f);
    while ((r + 1) * (r + 2) / 2 <= kblk) {
        r++;
    }
    while (r * (r + 1) / 2 > kblk) {
        r--;
    }
    int c = kblk - r * (r + 1) / 2;
    int bx = r;
    int by = c;
    int mult = (bx == by) ? 1 : 2;

    const __nv_bfloat16* Arows = g_xb + by * kBM * kD;
    const __nv_bfloat16* Brows = g_xb + bx * kBM * kD;

    __shared__ __align__(16) __nv_bfloat16 As[2][kBM][kLds];
    __shared__ __align__(16) __nv_bfloat16 Bs[2][kBM][kLds];

    int tid = threadIdx.x;
    int lane = tid & 31;
    int wid = tid >> 5;
    int warpM = wid & 3;
    int warpN = wid >> 2;
    int m0 = warpM * 32;
    int n0 = warpN * 64;

    // staging: 2 threads per row, each covers 2x 16B chunks per matrix
    int srow = tid >> 1;
    int sq = (tid & 1) * 2;

    float acc[2][8][4];
    for (int i = 0; i < 2; i++) {
        for (int j = 0; j < 8; j++) {
            for (int q = 0; q < 4; q++) {
                acc[i][j][q] = 0.f;
            }
        }
    }

    // prologue: stage chunk 0
    {
        const __nv_bfloat16* pa = Arows + srow * kD + sq * 8;
        const __nv_bfloat16* pb = Brows + srow * kD + sq * 8;
        cp16(&As[0][srow][sq * 8], pa);
        cp16(&As[0][srow][sq * 8 + 8], pa + 8);
        cp16(&Bs[0][srow][sq * 8], pb);
        cp16(&Bs[0][srow][sq * 8 + 8], pb + 8);
        cp_commit();
    }

    constexpr int kChunks = kD / kBK;   // 8
    for (int ck = 0; ck < kChunks; ck++) {
        if (ck + 1 < kChunks) {
            int nb = (ck + 1) & 1;
            int kk = (ck + 1) * kBK;
            const __nv_bfloat16* pa = Arows + srow * kD + kk + sq * 8;
            const __nv_bfloat16* pb = Brows + srow * kD + kk + sq * 8;
            cp16(&As[nb][srow][sq * 8], pa);
            cp16(&As[nb][srow][sq * 8 + 8], pa + 8);
            cp16(&Bs[nb][srow][sq * 8], pb);
            cp16(&Bs[nb][srow][sq * 8 + 8], pb + 8);
            cp_commit();
            cp_wait<1>();
        } else {
            cp_wait<0>();
        }
        __syncthreads();
        int cb = ck & 1;
        for (int k16 = 0; k16 < kBK; k16 += 16) {
            uint32_t afr[2][4];
            for (int mi = 0; mi < 2; mi++) {
                const __nv_bfloat16* pa =
                    &As[cb][m0 + mi * 16 + (lane & 15)][k16 + ((lane >> 4) & 1) * 8];
                ldmat_x4(afr[mi][0], afr[mi][1], afr[mi][2], afr[mi][3], pa);
            }
            uint32_t bfr[4][4];
            int quad = lane >> 3;
            int l7 = lane & 7;
            for (int g = 0; g < 4; g++) {
                const __nv_bfloat16* pb =
                    &Bs[cb][n0 + g * 16 + ((quad >> 1) & 1) * 8 + l7][k16 + (quad & 1) * 8];
                ldmat_x4(bfr[g][0], bfr[g][1], bfr[g][2], bfr[g][3], pb);
            }
            for (int mi = 0; mi < 2; mi++) {
                for (int nt = 0; nt < 8; nt++) {
                    int g = nt >> 1;
                    int ph = nt & 1;
                    mma_bf16(acc[mi][nt], afr[mi], bfr[g][ph * 2], bfr[g][ph * 2 + 1]);
                }
            }
        }
        __syncthreads();
    }

    float sqa[2][2];
    for (int mi = 0; mi < 2; mi++) {
        for (int h = 0; h < 2; h++) {
            sqa[mi][h] = g_rowsq[by * kBM + m0 + mi * 16 + (lane >> 2) + h * 8];
        }
    }
    float sqb[8][2];
    for (int nt = 0; nt < 8; nt++) {
        for (int j = 0; j < 2; j++) {
            sqb[nt][j] = g_rowsq[bx * kBM + n0 + nt * 8 + 2 * (lane & 3) + j];
        }
    }

    float s2[kNS];
    for (int q = 0; q < kNS; q++) {
        s2[q] = g_s2[q];
    }
    int cnt[kNS];
    for (int q = 0; q < kNS; q++) {
        cnt[q] = 0;
    }
    for (int mi = 0; mi < 2; mi++) {
        for (int nt = 0; nt < 8; nt++) {
            for (int q4 = 0; q4 < 4; q4++) {
                int h = q4 >> 1;
                int j = q4 & 1;
                float d2 = sqa[mi][h] + sqb[nt][j] - 2.0f * acc[mi][nt][q4];
                for (int q = 0; q < kNS; q++) {
                    cnt[q] += (d2 < s2[q]) ? 1 : 0;
                }
            }
        }
    }

    __shared__ int scnt[kNS];
    if (tid < kNS) {
        scnt[tid] = 0;
    }
    __syncthreads();
    for (int q = 0; q < kNS; q++) {
        int v = cnt[q];
        for (int o = 16; o > 0; o >>= 1) {
            v += __shfl_down_sync(0xffffffffu, v, o);
        }
        if (lane == 0) {
            atomicAdd(&scnt[q], v);
        }
    }
    __syncthreads();
    if (tid < kNS) {
        long long total = (long long)scnt[tid] * (long long)mult;
        atomicAdd(&g_corr_cnt[tid], (unsigned long long)total);
    }
}

// ---------------- K6: slopes + softmax-weighted output (1 thread) ----------------
__device__ double dslope(const double* xv, const double* yv, int n) {
    double xm = 0.0;
    double ym = 0.0;
    for (int i = 0; i < n; i++) {
        xm += xv[i];
        ym += yv[i];
    }
    xm /= n;
    ym /= n;
    double num = 0.0;
    double den = 0.0;
    for (int i = 0; i < n; i++) {
        double dx = xv[i] - xm;
        num += dx * (yv[i] - ym);
        den += dx * dx;
    }
    return num / den;
}

__global__ void k_final(const float* __restrict__ simp, float* __restrict__ outp) {
    double logs[kNS];
    double yb[kNS];
    double yc[kNS];
    double yi[kNS];
    for (int i = 0; i < kNS; i++) {
        logs[i] = log((double)(float)g_scales[i]);
        yb[i] = log((double)g_box_cnt[i]);
        yc[i] = log((double)g_corr_cnt[i]);
        unsigned long long tot = 0;
        for (int b = 0; b < g_scales[i]; b++) {
            tot += g_hist[i][b];
        }
        double ent = 0.0;
        for (int b = 0; b < g_scales[i]; b++) {
            if (g_hist[i][b] > 0) {
                double p = (double)g_hist[i][b] / (double)tot;
                ent -= p * log(p);
            }
        }
        yi[i] = ent;
    }
    double box_dim = -dslope(logs, yb, kNS);
    double corr_dim = dslope(logs, yc, kNS);
    double info_dim = dslope(logs, yi, kNS);

    float mx = simp[0];
    for (int i = 1; i < kNS; i++) {
        mx = fmaxf(mx, simp[i]);
    }
    double w[kNS];
    double den = 0.0;
    for (int i = 0; i < kNS; i++) {
        w[i] = exp((double)(simp[i] - mx));
        den += w[i];
    }
    double o = (w[0] * box_dim + w[1] * corr_dim + w[2] * info_dim) / den;
    outp[0] = (float)o;
}

// ---------------- launch ----------------
extern "C" void kernel_launch(void* const* d_in, const int* in_sizes, int n_in,
                              void* d_out, int out_size) {
    const float* x = (const float*)d_in[0];
    const float* sp = (const float*)d_in[1];
    const float* simp = (const float*)d_in[2];
    float* outp = (float*)d_out;

    k_init<<<1, 256>>>();
    k_statscvt<<<kN / 8, 256>>>(x);
    k_setup<<<1, 32>>>(sp);
    k_boxhist<<<kN / 8, 256>>>(x);
    int ntiles = kN / kBM;
    k_corr<<<ntiles * (ntiles + 1) / 2, 256>>>();
    k_final<<<1, 1>>>(simp, outp);
}

// round 7
// speedup vs baseline: 3.6680x; 1.0209x over previous
#include <cuda_runtime.h>
#include <cuda_bf16.h>
#include <math.h>
#include <stdint.h>

constexpr int kN   = 8192;   // points
constexpr int kD   = 256;    // dim
constexpr int kNS  = 5;      // scales
constexpr int kBM  = 128;    // block tile (M and N)
constexpr int kBK  = 32;     // k tile
constexpr int kLds = 40;     // smem row stride in bf16 elems (32 + 8 pad)
constexpr int kStages = 3;
constexpr int kTileElems = kBM * kLds;                       // per matrix per stage
constexpr int kSmemBytes = kStages * kTileElems * 2 * 2;     // A+B, bf16 -> 61440

// ---------------- device scratch (no allocations allowed) ----------------
__device__ double g_sumsq;
__device__ double g_colsum[kD];
__device__ unsigned int g_minbits;
__device__ unsigned int g_maxbits;
__device__ float  g_rowsq[kN];
__device__ __nv_bfloat16 g_xb[kN * kD];
__device__ int    g_scales[kNS];
__device__ float  g_s2[kNS];
__device__ float  g_boxthr[kNS];
__device__ float  g_hmin;
__device__ float  g_hrange;
__device__ unsigned long long g_box_cnt[kNS];
__device__ unsigned long long g_corr_cnt[kNS];
__device__ unsigned long long g_hist[kNS][16];

__device__ __forceinline__ unsigned f2mono(float f) {
    unsigned u = __float_as_uint(f);
    return (u & 0x80000000u) ? ~u : (u | 0x80000000u);
}
__device__ __forceinline__ float mono2f(unsigned u) {
    unsigned b = (u & 0x80000000u) ? (u & 0x7fffffffu) : ~u;
    return __uint_as_float(b);
}

// ---------------- K0: zero scratch (graph replays => must re-init) ----------------
__global__ void k_init() {
    int t = threadIdx.x;
    if (t == 0) {
        g_sumsq = 0.0;
        g_minbits = 0xFFFFFFFFu;
        g_maxbits = 0u;
    }
    if (t < kD) {
        g_colsum[t] = 0.0;
    }
    if (t < kNS) {
        g_box_cnt[t] = 0ull;
        g_corr_cnt[t] = 0ull;
    }
    if (t < kNS * 16) {
        ((unsigned long long*)g_hist)[t] = 0ull;
    }
}

// ---------------- K1: fused stats + bf16 conversion + row norms ----------------
__global__ void k_statscvt(const float* __restrict__ x) {
    __shared__ double scol[kD];
    __shared__ double ssq[256];
    __shared__ unsigned smin[256];
    __shared__ unsigned smax[256];
    int t = threadIdx.x;
    int w = t >> 5;
    int lane = t & 31;
    int row = blockIdx.x * 8 + w;

    scol[t] = 0.0;
    __syncthreads();

    const float4* xr = (const float4*)(x + row * kD);
    float4 a = xr[lane];
    float4 b = xr[lane + 32];

    float s = a.x * a.x + a.y * a.y + a.z * a.z + a.w * a.w
            + b.x * b.x + b.y * b.y + b.z * b.z + b.w * b.w;
    for (int o = 16; o > 0; o >>= 1) {
        s += __shfl_down_sync(0xffffffffu, s, o);
    }
    if (lane == 0) {
        g_rowsq[row] = s;
    }

    __nv_bfloat162* dst = (__nv_bfloat162*)(g_xb + row * kD);
    dst[lane * 2 + 0] = __floats2bfloat162_rn(a.x, a.y);
    dst[lane * 2 + 1] = __floats2bfloat162_rn(a.z, a.w);
    dst[64 + lane * 2 + 0] = __floats2bfloat162_rn(b.x, b.y);
    dst[64 + lane * 2 + 1] = __floats2bfloat162_rn(b.z, b.w);

    atomicAdd(&scol[lane * 4 + 0], (double)a.x);
    atomicAdd(&scol[lane * 4 + 1], (double)a.y);
    atomicAdd(&scol[lane * 4 + 2], (double)a.z);
    atomicAdd(&scol[lane * 4 + 3], (double)a.w);
    atomicAdd(&scol[128 + lane * 4 + 0], (double)b.x);
    atomicAdd(&scol[128 + lane * 4 + 1], (double)b.y);
    atomicAdd(&scol[128 + lane * 4 + 2], (double)b.z);
    atomicAdd(&scol[128 + lane * 4 + 3], (double)b.w);

    double lq = (double)a.x * a.x + (double)a.y * a.y + (double)a.z * a.z + (double)a.w * a.w
              + (double)b.x * b.x + (double)b.y * b.y + (double)b.z * b.z + (double)b.w * b.w;
    unsigned lmin = min(min(min(f2mono(a.x), f2mono(a.y)), min(f2mono(a.z), f2mono(a.w))),
                        min(min(f2mono(b.x), f2mono(b.y)), min(f2mono(b.z), f2mono(b.w))));
    unsigned lmax = max(max(max(f2mono(a.x), f2mono(a.y)), max(f2mono(a.z), f2mono(a.w))),
                        max(max(f2mono(b.x), f2mono(b.y)), max(f2mono(b.z), f2mono(b.w))));
    ssq[t] = lq;
    smin[t] = lmin;
    smax[t] = lmax;
    __syncthreads();
    for (int o = 128; o > 0; o >>= 1) {
        if (t < o) {
            ssq[t] += ssq[t + o];
            smin[t] = min(smin[t], smin[t + o]);
            smax[t] = max(smax[t], smax[t + o]);
        }
        __syncthreads();
    }
    if (t == 0) {
        atomicAdd(&g_sumsq, ssq[0]);
        atomicMin(&g_minbits, smin[0]);
        atomicMax(&g_maxbits, smax[0]);
    }
    atomicAdd(&g_colsum[t], scol[t]);
}

// ---------------- K2: scales + thresholds (single warp) ----------------
__global__ void k_setup(const float* __restrict__ scale_params) {
    int lane = threadIdx.x;

    double p = g_colsum[lane] + g_colsum[lane + 32] + g_colsum[lane + 64] + g_colsum[lane + 96]
             + g_colsum[lane + 128] + g_colsum[lane + 160] + g_colsum[lane + 192] + g_colsum[lane + 224];
    for (int o = 16; o > 0; o >>= 1) {
        p += __shfl_down_sync(0xffffffffu, p, o);
    }
    double tot = __shfl_sync(0xffffffffu, p, 0);

    int scl = 0;
    if (lane < kNS) {
        double nd = (double)kN * (double)kD;
        double mean = tot / nd;
        double var = (g_sumsq - nd * mean * mean) / (nd - 1.0);
        double sf = sqrt(var) / mean;
        sf = fmin(fmax(sf, 0.5), 2.0);
        double v = exp((double)scale_params[lane]) * sf;
        v = fmin(fmax(v, 2.0), 16.0);
        scl = (int)v;
        g_scales[lane] = scl;
        g_s2[lane] = (float)(scl * scl);
    }
    if (lane == 0) {
        float mn = mono2f(g_minbits);
        float mx = mono2f(g_maxbits);
        g_hmin = mn;
        g_hrange = mx - mn;
    }

    for (int i = 0; i < kNS; i++) {
        int s = __shfl_sync(0xffffffffu, scl, i);
        int n = (kD / s) * s;
        double q = 0.0;
        for (int j = lane; j < n; j += 32) {
            q += g_colsum[j];
        }
        for (int o = 16; o > 0; o >>= 1) {
            q += __shfl_down_sync(0xffffffffu, q, o);
        }
        if (lane == 0) {
            g_boxthr[i] = (float)(q / ((double)kN * (double)n));
        }
    }
}

// ---------------- K3: fused box counting + histograms (one pass over x) ----------------
__global__ void k_boxhist(const float* __restrict__ x) {
    __shared__ float sr[8][kD];
    __shared__ float pf[8][kD + 8];
    __shared__ int sh[kNS][16];
    __shared__ int sbox[kNS];
    __shared__ float sthr[kNS];
    __shared__ int sscl[kNS];
    int t = threadIdx.x;
    int base = blockIdx.x * 8 * kD;
    for (int i = t; i < 8 * kD; i += 256) {
        ((float*)sr)[i] = x[base + i];
    }
    if (t < kNS * 16) {
        ((int*)sh)[t] = 0;
    }
    if (t < kNS) {
        sbox[t] = 0;
        sthr[t] = g_boxthr[t];
        sscl[t] = g_scales[t];
    }
    __syncthreads();

    int w = t >> 5;
    int lane = t & 31;

    // per-row prefix sums (warp w owns row w): each lane scans 8 consecutive values
    {
        float run = 0.f;
        float incl[8];
        for (int i = 0; i < 8; i++) {
            run += sr[w][lane * 8 + i];
            incl[i] = run;
        }
        float tsum = run;
        for (int o = 1; o < 32; o <<= 1) {
            float y = __shfl_up_sync(0xffffffffu, tsum, o);
            if (lane >= o) {
                tsum += y;
            }
        }
        float basep = tsum - run;
        for (int i = 0; i < 8; i++) {
            pf[w][lane * 8 + i + 1] = basep + incl[i];
        }
        if (lane == 0) {
            pf[w][0] = 0.f;
        }
        __syncwarp();
    }

    // box counting via prefix differences (skip duplicate scales)
    for (int si = 0; si < kNS; si++) {
        int s = sscl[si];
        if (si > 0 && s == sscl[si - 1]) {
            continue;
        }
        float thr = sthr[si];
        int m = kD / s;
        float inv = 1.0f / (float)s;
        int cnt = 0;
        for (int g = lane; g < m; g += 32) {
            float sum = pf[w][g * s + s] - pf[w][g * s];
            cnt += (sum * inv > thr) ? 1 : 0;
        }
        cnt = __reduce_add_sync(0xffffffffu, cnt);
        if (lane == 0) {
            atomicAdd(&sbox[si], cnt);
        }
    }

    // histograms via match_any, skipping duplicate scales
    float mn = g_hmin;
    float rng = g_hrange;
    float invr = (rng > 0.f) ? (1.0f / rng) : 0.f;
    for (int i = 0; i < 8; i++) {
        float v = ((const float*)sr)[t + i * 256];
        float u = (v - mn) * invr;
        for (int si = 0; si < kNS; si++) {
            int s = sscl[si];
            if (si > 0 && s == sscl[si - 1]) {
                continue;
            }
            int b = (int)(u * (float)s);
            b = min(b, s - 1);
            b = max(b, 0);
            unsigned msk = __match_any_sync(0xffffffffu, b);
            int leader = __ffs(msk) - 1;
            if (lane == leader) {
                atomicAdd(&sh[si][b], __popc(msk));
            }
        }
    }
    __syncthreads();
    // writeback with duplicate-scale canonicalization
    if (t < kNS) {
        int c = t;
        while (c > 0 && sscl[c] == sscl[c - 1]) {
            c--;
        }
        atomicAdd(&g_box_cnt[t], (unsigned long long)sbox[c]);
    }
    if (t < kNS * 16) {
        int si = t >> 4;
        int b = t & 15;
        int c = si;
        while (c > 0 && sscl[c] == sscl[c - 1]) {
            c--;
        }
        int v = sh[c][b];
        if (v != 0) {
            atomicAdd(&((unsigned long long*)g_hist)[t], (unsigned long long)v);
        }
    }
}

// ---------------- K5: pairwise distance counts via bf16 tensor cores ----------------
__device__ __forceinline__ void ldmat_x4(uint32_t& r0, uint32_t& r1,
                                         uint32_t& r2, uint32_t& r3,
                                         const __nv_bfloat16* p) {
    uint32_t addr = (uint32_t)__cvta_generic_to_shared(p);
    asm volatile(
        "ldmatrix.sync.aligned.m8n8.x4.shared.b16 {%0,%1,%2,%3}, [%4];"
        : "=r"(r0), "=r"(r1), "=r"(r2), "=r"(r3)
        : "r"(addr));
}

__device__ __forceinline__ void mma_bf16(float* c, const uint32_t* a,
                                         uint32_t b0, uint32_t b1) {
    asm volatile(
        "mma.sync.aligned.m16n8k16.row.col.f32.bf16.bf16.f32 "
        "{%0,%1,%2,%3}, {%4,%5,%6,%7}, {%8,%9}, {%0,%1,%2,%3};"
        : "+f"(c[0]), "+f"(c[1]), "+f"(c[2]), "+f"(c[3])
        : "r"(a[0]), "r"(a[1]), "r"(a[2]), "r"(a[3]), "r"(b0), "r"(b1));
}

__device__ __forceinline__ void cp16(void* sp, const void* gp) {
    uint32_t a = (uint32_t)__cvta_generic_to_shared(sp);
    asm volatile("cp.async.ca.shared.global [%0], [%1], 16;" :: "r"(a), "l"(gp));
}
__device__ __forceinline__ void cp_commit() {
    asm volatile("cp.async.commit_group;");
}
template <int n>
__device__ __forceinline__ void cp_wait() {
    asm volatile("cp.async.wait_group %0;" :: "n"(n));
}

__global__ void __launch_bounds__(256, 2) k_corr() {
    extern __shared__ __align__(16) __nv_bfloat16 smem[];
    __nv_bfloat16* As = smem;                              // [kStages][kBM][kLds]
    __nv_bfloat16* Bs = smem + kStages * kTileElems;       // [kStages][kBM][kLds]

    int kblk = blockIdx.x;
    int r = (int)((sqrtf(8.0f * (float)kblk + 1.0f) - 1.0f) * 0.5f);
    while ((r + 1) * (r + 2) / 2 <= kblk) {
        r++;
    }
    while (r * (r + 1) / 2 > kblk) {
        r--;
    }
    int c = kblk - r * (r + 1) / 2;
    int bx = r;
    int by = c;
    int mult = (bx == by) ? 1 : 2;

    const __nv_bfloat16* Arows = g_xb + by * kBM * kD;
    const __nv_bfloat16* Brows = g_xb + bx * kBM * kD;

    int tid = threadIdx.x;
    int lane = tid & 31;
    int wid = tid >> 5;
    int warpM = wid & 3;
    int warpN = wid >> 2;
    int m0 = warpM * 32;
    int n0 = warpN * 64;

    // staging: 2 threads per row, each covers 2x 16B chunks per matrix
    int srow = tid >> 1;
    int sq = (tid & 1) * 2;
    const __nv_bfloat16* ga = Arows + srow * kD + sq * 8;
    const __nv_bfloat16* gb = Brows + srow * kD + sq * 8;
    int soff = srow * kLds + sq * 8;

    float acc[2][8][4];
    for (int i = 0; i < 2; i++) {
        for (int j = 0; j < 8; j++) {
            for (int q = 0; q < 4; q++) {
                acc[i][j][q] = 0.f;
            }
        }
    }

    constexpr int kChunks = kD / kBK;   // 8

    // prologue: stage chunks 0 and 1
    for (int ps = 0; ps < 2; ps++) {
        int kk = ps * kBK;
        __nv_bfloat16* sa = As + ps * kTileElems + soff;
        __nv_bfloat16* sb = Bs + ps * kTileElems + soff;
        cp16(sa, ga + kk);
        cp16(sa + 8, ga + kk + 8);
        cp16(sb, gb + kk);
        cp16(sb + 8, gb + kk + 8);
        cp_commit();
    }

    for (int ck = 0; ck < kChunks; ck++) {
        if (ck < kChunks - 1) {
            cp_wait<1>();
        } else {
            cp_wait<0>();
        }
        __syncthreads();
        if (ck + 2 < kChunks) {
            int nb = (ck + 2) % kStages;
            int kk = (ck + 2) * kBK;
            __nv_bfloat16* sa = As + nb * kTileElems + soff;
            __nv_bfloat16* sb = Bs + nb * kTileElems + soff;
            cp16(sa, ga + kk);
            cp16(sa + 8, ga + kk + 8);
            cp16(sb, gb + kk);
            cp16(sb + 8, gb + kk + 8);
            cp_commit();
        }
        int cb = ck % kStages;
        const __nv_bfloat16* Ab = As + cb * kTileElems;
        const __nv_bfloat16* Bb = Bs + cb * kTileElems;
        for (int k16 = 0; k16 < kBK; k16 += 16) {
            uint32_t afr[2][4];
            for (int mi = 0; mi < 2; mi++) {
                const __nv_bfloat16* pa =
                    Ab + (m0 + mi * 16 + (lane & 15)) * kLds + k16 + ((lane >> 4) & 1) * 8;
                ldmat_x4(afr[mi][0], afr[mi][1], afr[mi][2], afr[mi][3], pa);
            }
            uint32_t bfr[4][4];
            int quad = lane >> 3;
            int l7 = lane & 7;
            for (int g = 0; g < 4; g++) {
                const __nv_bfloat16* pb =
                    Bb + (n0 + g * 16 + ((quad >> 1) & 1) * 8 + l7) * kLds + k16 + (quad & 1) * 8;
                ldmat_x4(bfr[g][0], bfr[g][1], bfr[g][2], bfr[g][3], pb);
            }
            for (int mi = 0; mi < 2; mi++) {
                for (int nt = 0; nt < 8; nt++) {
                    int g = nt >> 1;
                    int ph = nt & 1;
                    mma_bf16(acc[mi][nt], afr[mi], bfr[g][ph * 2], bfr[g][ph * 2 + 1]);
                }
            }
        }
    }

    float sqa[2][2];
    for (int mi = 0; mi < 2; mi++) {
        for (int h = 0; h < 2; h++) {
            sqa[mi][h] = g_rowsq[by * kBM + m0 + mi * 16 + (lane >> 2) + h * 8];
        }
    }
    float sqb[8][2];
    for (int nt = 0; nt < 8; nt++) {
        for (int j = 0; j < 2; j++) {
            sqb[nt][j] = g_rowsq[bx * kBM + n0 + nt * 8 + 2 * (lane & 3) + j];
        }
    }

    float s2[kNS];
    for (int q = 0; q < kNS; q++) {
        s2[q] = g_s2[q];
    }
    int cnt[kNS];
    for (int q = 0; q < kNS; q++) {
        cnt[q] = 0;
    }
    for (int mi = 0; mi < 2; mi++) {
        for (int nt = 0; nt < 8; nt++) {
            for (int q4 = 0; q4 < 4; q4++) {
                int h = q4 >> 1;
                int j = q4 & 1;
                float d2 = sqa[mi][h] + sqb[nt][j] - 2.0f * acc[mi][nt][q4];
                for (int q = 0; q < kNS; q++) {
                    cnt[q] += (d2 < s2[q]) ? 1 : 0;
                }
            }
        }
    }

    __shared__ int scnt[kNS];
    if (tid < kNS) {
        scnt[tid] = 0;
    }
    __syncthreads();
    for (int q = 0; q < kNS; q++) {
        int v = __reduce_add_sync(0xffffffffu, cnt[q]);
        if (lane == 0) {
            atomicAdd(&scnt[q], v);
        }
    }
    __syncthreads();
    if (tid < kNS) {
        long long total = (long long)scnt[tid] * (long long)mult;
        atomicAdd(&g_corr_cnt[tid], (unsigned long long)total);
    }
}

// ---------------- K6: slopes + softmax-weighted output (1 thread) ----------------
__device__ double dslope(const double* xv, const double* yv, int n) {
    double xm = 0.0;
    double ym = 0.0;
    for (int i = 0; i < n; i++) {
        xm += xv[i];
        ym += yv[i];
    }
    xm /= n;
    ym /= n;
    double num = 0.0;
    double den = 0.0;
    for (int i = 0; i < n; i++) {
        double dx = xv[i] - xm;
        num += dx * (yv[i] - ym);
        den += dx * dx;
    }
    return num / den;
}

__global__ void k_final(const float* __restrict__ simp, float* __restrict__ outp) {
    double logs[kNS];
    double yb[kNS];
    double yc[kNS];
    double yi[kNS];
    for (int i = 0; i < kNS; i++) {
        logs[i] = log((double)(float)g_scales[i]);
        yb[i] = log((double)g_box_cnt[i]);
        yc[i] = log((double)g_corr_cnt[i]);
        unsigned long long tot = 0;
        for (int b = 0; b < g_scales[i]; b++) {
            tot += g_hist[i][b];
        }
        double ent = 0.0;
        for (int b = 0; b < g_scales[i]; b++) {
            if (g_hist[i][b] > 0) {
                double p = (double)g_hist[i][b] / (double)tot;
                ent -= p * log(p);
            }
        }
        yi[i] = ent;
    }
    double box_dim = -dslope(logs, yb, kNS);
    double corr_dim = dslope(logs, yc, kNS);
    double info_dim = dslope(logs, yi, kNS);

    float mx = simp[0];
    for (int i = 1; i < kNS; i++) {
        mx = fmaxf(mx, simp[i]);
    }
    double w[kNS];
    double den = 0.0;
    for (int i = 0; i < kNS; i++) {
        w[i] = exp((double)(simp[i] - mx));
        den += w[i];
    }
    double o = (w[0] * box_dim + w[1] * corr_dim + w[2] * info_dim) / den;
    outp[0] = (float)o;
}

// ---------------- launch ----------------
extern "C" void kernel_launch(void* const* d_in, const int* in_sizes, int n_in,
                              void* d_out, int out_size) {
    const float* x = (const float*)d_in[0];
    const float* sp = (const float*)d_in[1];
    const float* simp = (const float*)d_in[2];
    float* outp = (float*)d_out;

    cudaFuncSetAttribute(k_corr, cudaFuncAttributeMaxDynamicSharedMemorySize, kSmemBytes);

    k_init<<<1, 256>>>();
    k_statscvt<<<kN / 8, 256>>>(x);
    k_setup<<<1, 32>>>(sp);
    k_boxhist<<<kN / 8, 256>>>(x);
    int ntiles = kN / kBM;
    k_corr<<<ntiles * (ntiles + 1) / 2, 256, kSmemBytes>>>();
    k_final<<<1, 1>>>(simp, outp);
}

// round 8
// speedup vs baseline: 4.0475x; 1.1035x over previous
#include <cuda_runtime.h>
#include <cuda_bf16.h>
#include <math.h>
#include <stdint.h>

constexpr int kN   = 8192;   // points
constexpr int kD   = 256;    // dim
constexpr int kNS  = 5;      // scales
constexpr int kBM  = 128;    // block tile (M and N)
constexpr int kBK  = 32;     // k tile
constexpr int kLds = 40;     // smem row stride in bf16 elems (32 + 8 pad)
constexpr int kStages = 3;
constexpr int kTileElems = kBM * kLds;                       // per matrix per stage
constexpr int kSmemBytes = kStages * kTileElems * 2 * 2;     // A+B, bf16 -> 61440

// ---------------- device scratch (no allocations allowed) ----------------
__device__ double g_sumsq;
__device__ double g_colsum[kD];
__device__ unsigned int g_minbits;
__device__ unsigned int g_maxbits;
__device__ float  g_rowsq[kN];
__device__ __nv_bfloat16 g_xb[kN * kD];
__device__ int    g_scales[kNS];
__device__ float  g_s2[kNS];
__device__ float  g_boxthr[kNS];
__device__ float  g_hmin;
__device__ float  g_hrange;
__device__ unsigned long long g_box_cnt[kNS];
__device__ unsigned long long g_corr_cnt[kNS];
__device__ unsigned long long g_hist[kNS][16];

__device__ __forceinline__ unsigned f2mono(float f) {
    unsigned u = __float_as_uint(f);
    return (u & 0x80000000u) ? ~u : (u | 0x80000000u);
}
__device__ __forceinline__ float mono2f(unsigned u) {
    unsigned b = (u & 0x80000000u) ? (u & 0x7fffffffu) : ~u;
    return __uint_as_float(b);
}

// ---------------- K0: zero scratch (graph replays => must re-init) ----------------
__global__ void k_init() {
    int t = threadIdx.x;
    if (t == 0) {
        g_sumsq = 0.0;
        g_minbits = 0xFFFFFFFFu;
        g_maxbits = 0u;
    }
    if (t < kD) {
        g_colsum[t] = 0.0;
    }
    if (t < kNS) {
        g_box_cnt[t] = 0ull;
        g_corr_cnt[t] = 0ull;
    }
    if (t < kNS * 16) {
        ((unsigned long long*)g_hist)[t] = 0ull;
    }
}

// ---------------- K1: fused stats + bf16 conversion + row norms ----------------
__global__ void k_statscvt(const float* __restrict__ x) {
    __shared__ double scol[kD];
    __shared__ double ssq[256];
    __shared__ unsigned smin[256];
    __shared__ unsigned smax[256];
    int t = threadIdx.x;
    int w = t >> 5;
    int lane = t & 31;
    int row = blockIdx.x * 8 + w;

    scol[t] = 0.0;
    __syncthreads();

    const float4* xr = (const float4*)(x + row * kD);
    float4 a = xr[lane];
    float4 b = xr[lane + 32];

    float s = a.x * a.x + a.y * a.y + a.z * a.z + a.w * a.w
            + b.x * b.x + b.y * b.y + b.z * b.z + b.w * b.w;
    for (int o = 16; o > 0; o >>= 1) {
        s += __shfl_down_sync(0xffffffffu, s, o);
    }
    if (lane == 0) {
        g_rowsq[row] = s;
    }

    __nv_bfloat162* dst = (__nv_bfloat162*)(g_xb + row * kD);
    dst[lane * 2 + 0] = __floats2bfloat162_rn(a.x, a.y);
    dst[lane * 2 + 1] = __floats2bfloat162_rn(a.z, a.w);
    dst[64 + lane * 2 + 0] = __floats2bfloat162_rn(b.x, b.y);
    dst[64 + lane * 2 + 1] = __floats2bfloat162_rn(b.z, b.w);

    atomicAdd(&scol[lane * 4 + 0], (double)a.x);
    atomicAdd(&scol[lane * 4 + 1], (double)a.y);
    atomicAdd(&scol[lane * 4 + 2], (double)a.z);
    atomicAdd(&scol[lane * 4 + 3], (double)a.w);
    atomicAdd(&scol[128 + lane * 4 + 0], (double)b.x);
    atomicAdd(&scol[128 + lane * 4 + 1], (double)b.y);
    atomicAdd(&scol[128 + lane * 4 + 2], (double)b.z);
    atomicAdd(&scol[128 + lane * 4 + 3], (double)b.w);

    double lq = (double)a.x * a.x + (double)a.y * a.y + (double)a.z * a.z + (double)a.w * a.w
              + (double)b.x * b.x + (double)b.y * b.y + (double)b.z * b.z + (double)b.w * b.w;
    unsigned lmin = min(min(min(f2mono(a.x), f2mono(a.y)), min(f2mono(a.z), f2mono(a.w))),
                        min(min(f2mono(b.x), f2mono(b.y)), min(f2mono(b.z), f2mono(b.w))));
    unsigned lmax = max(max(max(f2mono(a.x), f2mono(a.y)), max(f2mono(a.z), f2mono(a.w))),
                        max(max(f2mono(b.x), f2mono(b.y)), max(f2mono(b.z), f2mono(b.w))));
    ssq[t] = lq;
    smin[t] = lmin;
    smax[t] = lmax;
    __syncthreads();
    for (int o = 128; o > 0; o >>= 1) {
        if (t < o) {
            ssq[t] += ssq[t + o];
            smin[t] = min(smin[t], smin[t + o]);
            smax[t] = max(smax[t], smax[t + o]);
        }
        __syncthreads();
    }
    if (t == 0) {
        atomicAdd(&g_sumsq, ssq[0]);
        atomicMin(&g_minbits, smin[0]);
        atomicMax(&g_maxbits, smax[0]);
    }
    atomicAdd(&g_colsum[t], scol[t]);
}

// ---------------- K2: scales + thresholds (single warp) ----------------
__global__ void k_setup(const float* __restrict__ scale_params) {
    int lane = threadIdx.x;

    double p = g_colsum[lane] + g_colsum[lane + 32] + g_colsum[lane + 64] + g_colsum[lane + 96]
             + g_colsum[lane + 128] + g_colsum[lane + 160] + g_colsum[lane + 192] + g_colsum[lane + 224];
    for (int o = 16; o > 0; o >>= 1) {
        p += __shfl_down_sync(0xffffffffu, p, o);
    }
    double tot = __shfl_sync(0xffffffffu, p, 0);

    int scl = 0;
    if (lane < kNS) {
        double nd = (double)kN * (double)kD;
        double mean = tot / nd;
        double var = (g_sumsq - nd * mean * mean) / (nd - 1.0);
        double sf = sqrt(var) / mean;
        sf = fmin(fmax(sf, 0.5), 2.0);
        double v = exp((double)scale_params[lane]) * sf;
        v = fmin(fmax(v, 2.0), 16.0);
        scl = (int)v;
        g_scales[lane] = scl;
        g_s2[lane] = (float)(scl * scl);
    }
    if (lane == 0) {
        float mn = mono2f(g_minbits);
        float mx = mono2f(g_maxbits);
        g_hmin = mn;
        g_hrange = mx - mn;
    }

    for (int i = 0; i < kNS; i++) {
        int s = __shfl_sync(0xffffffffu, scl, i);
        int n = (kD / s) * s;
        double q = 0.0;
        for (int j = lane; j < n; j += 32) {
            q += g_colsum[j];
        }
        for (int o = 16; o > 0; o >>= 1) {
            q += __shfl_down_sync(0xffffffffu, q, o);
        }
        if (lane == 0) {
            g_boxthr[i] = (float)(q / ((double)kN * (double)n));
        }
    }
}

// ---------------- K3: fused box counting + histograms (register-resident) ----------------
__global__ void k_boxhist(const float* __restrict__ x) {
    __shared__ float pf[8][kD + 8];
    __shared__ int sh[kNS][16];
    __shared__ int sbox[kNS];
    __shared__ float sthr[kNS];
    __shared__ int sscl[kNS];
    int t = threadIdx.x;
    int w = t >> 5;
    int lane = t & 31;
    int row = blockIdx.x * 8 + w;

    if (t < kNS * 16) {
        ((int*)sh)[t] = 0;
    }
    if (t < kNS) {
        sbox[t] = 0;
        sthr[t] = g_boxthr[t];
        sscl[t] = g_scales[t];
    }

    // each lane owns 8 consecutive elements of its warp's row
    const float4* xr = (const float4*)(x + row * kD);
    float4 va = xr[lane * 2];
    float4 vb = xr[lane * 2 + 1];
    float v[8];
    v[0] = va.x; v[1] = va.y; v[2] = va.z; v[3] = va.w;
    v[4] = vb.x; v[5] = vb.y; v[6] = vb.z; v[7] = vb.w;

    // per-row prefix sums
    {
        float run = 0.f;
        float incl[8];
        for (int i = 0; i < 8; i++) {
            run += v[i];
            incl[i] = run;
        }
        float tsum = run;
        for (int o = 1; o < 32; o <<= 1) {
            float y = __shfl_up_sync(0xffffffffu, tsum, o);
            if (lane >= o) {
                tsum += y;
            }
        }
        float basep = tsum - run;
        for (int i = 0; i < 8; i++) {
            pf[w][lane * 8 + i + 1] = basep + incl[i];
        }
        if (lane == 0) {
            pf[w][0] = 0.f;
        }
    }
    __syncthreads();   // also covers sh/sbox/sthr/sscl init

    // box counting via prefix differences (skip duplicate scales)
    for (int si = 0; si < kNS; si++) {
        int s = sscl[si];
        if (si > 0 && s == sscl[si - 1]) {
            continue;
        }
        float thr = sthr[si];
        int m = kD / s;
        float inv = 1.0f / (float)s;
        int cnt = 0;
        for (int g = lane; g < m; g += 32) {
            float sum = pf[w][g * s + s] - pf[w][g * s];
            cnt += (sum * inv > thr) ? 1 : 0;
        }
        cnt = __reduce_add_sync(0xffffffffu, cnt);
        if (lane == 0) {
            atomicAdd(&sbox[si], cnt);
        }
    }

    // histograms via match_any from registers, skipping duplicate scales
    float mn = g_hmin;
    float rng = g_hrange;
    float invr = (rng > 0.f) ? (1.0f / rng) : 0.f;
    for (int i = 0; i < 8; i++) {
        float u = (v[i] - mn) * invr;
        for (int si = 0; si < kNS; si++) {
            int s = sscl[si];
            if (si > 0 && s == sscl[si - 1]) {
                continue;
            }
            int b = (int)(u * (float)s);
            b = min(b, s - 1);
            b = max(b, 0);
            unsigned msk = __match_any_sync(0xffffffffu, b);
            int leader = __ffs(msk) - 1;
            if (lane == leader) {
                atomicAdd(&sh[si][b], __popc(msk));
            }
        }
    }
    __syncthreads();
    // writeback with duplicate-scale canonicalization
    if (t < kNS) {
        int c = t;
        while (c > 0 && sscl[c] == sscl[c - 1]) {
            c--;
        }
        atomicAdd(&g_box_cnt[t], (unsigned long long)sbox[c]);
    }
    if (t < kNS * 16) {
        int si = t >> 4;
        int b = t & 15;
        int c = si;
        while (c > 0 && sscl[c] == sscl[c - 1]) {
            c--;
        }
        int vv = sh[c][b];
        if (vv != 0) {
            atomicAdd(&((unsigned long long*)g_hist)[t], (unsigned long long)vv);
        }
    }
}

// ---------------- K5: pairwise distance counts via bf16 tensor cores ----------------
__device__ __forceinline__ void ldmat_x4(uint32_t& r0, uint32_t& r1,
                                         uint32_t& r2, uint32_t& r3,
                                         const __nv_bfloat16* p) {
    uint32_t addr = (uint32_t)__cvta_generic_to_shared(p);
    asm volatile(
        "ldmatrix.sync.aligned.m8n8.x4.shared.b16 {%0,%1,%2,%3}, [%4];"
        : "=r"(r0), "=r"(r1), "=r"(r2), "=r"(r3)
        : "r"(addr));
}

__device__ __forceinline__ void mma_bf16(float* c, const uint32_t* a,
                                         uint32_t b0, uint32_t b1) {
    asm volatile(
        "mma.sync.aligned.m16n8k16.row.col.f32.bf16.bf16.f32 "
        "{%0,%1,%2,%3}, {%4,%5,%6,%7}, {%8,%9}, {%0,%1,%2,%3};"
        : "+f"(c[0]), "+f"(c[1]), "+f"(c[2]), "+f"(c[3])
        : "r"(a[0]), "r"(a[1]), "r"(a[2]), "r"(a[3]), "r"(b0), "r"(b1));
}

__device__ __forceinline__ void cp16(void* sp, const void* gp) {
    uint32_t a = (uint32_t)__cvta_generic_to_shared(sp);
    asm volatile("cp.async.ca.shared.global [%0], [%1], 16;" :: "r"(a), "l"(gp));
}
__device__ __forceinline__ void cp_commit() {
    asm volatile("cp.async.commit_group;");
}
template <int n>
__device__ __forceinline__ void cp_wait() {
    asm volatile("cp.async.wait_group %0;" :: "n"(n));
}

__global__ void __launch_bounds__(256, 2) k_corr() {
    extern __shared__ __align__(16) __nv_bfloat16 smem[];
    __nv_bfloat16* As = smem;                              // [kStages][kBM][kLds]
    __nv_bfloat16* Bs = smem + kStages * kTileElems;       // [kStages][kBM][kLds]

    int kblk = blockIdx.x;
    int r = (int)((sqrtf(8.0f * (float)kblk + 1.0f) - 1.0f) * 0.5f);
    while ((r + 1) * (r + 2) / 2 <= kblk) {
        r++;
    }
    while (r * (r + 1) / 2 > kblk) {
        r--;
    }
    int c = kblk - r * (r + 1) / 2;
    int bx = r;
    int by = c;
    int mult = (bx == by) ? 1 : 2;

    const __nv_bfloat16* Arows = g_xb + by * kBM * kD;
    const __nv_bfloat16* Brows = g_xb + bx * kBM * kD;

    int tid = threadIdx.x;
    int lane = tid & 31;
    int wid = tid >> 5;
    int warpM = wid & 3;
    int warpN = wid >> 2;
    int m0 = warpM * 32;
    int n0 = warpN * 64;

    int srow = tid >> 1;
    int sq = (tid & 1) * 2;
    const __nv_bfloat16* ga = Arows + srow * kD + sq * 8;
    const __nv_bfloat16* gb = Brows + srow * kD + sq * 8;
    int soff = srow * kLds + sq * 8;

    float acc[2][8][4];
    for (int i = 0; i < 2; i++) {
        for (int j = 0; j < 8; j++) {
            for (int q = 0; q < 4; q++) {
                acc[i][j][q] = 0.f;
            }
        }
    }

    constexpr int kChunks = kD / kBK;   // 8

    for (int ps = 0; ps < 2; ps++) {
        int kk = ps * kBK;
        __nv_bfloat16* sa = As + ps * kTileElems + soff;
        __nv_bfloat16* sb = Bs + ps * kTileElems + soff;
        cp16(sa, ga + kk);
        cp16(sa + 8, ga + kk + 8);
        cp16(sb, gb + kk);
        cp16(sb + 8, gb + kk + 8);
        cp_commit();
    }

    for (int ck = 0; ck < kChunks; ck++) {
        if (ck < kChunks - 1) {
            cp_wait<1>();
        } else {
            cp_wait<0>();
        }
        __syncthreads();
        if (ck + 2 < kChunks) {
            int nb = (ck + 2) % kStages;
            int kk = (ck + 2) * kBK;
            __nv_bfloat16* sa = As + nb * kTileElems + soff;
            __nv_bfloat16* sb = Bs + nb * kTileElems + soff;
            cp16(sa, ga + kk);
            cp16(sa + 8, ga + kk + 8);
            cp16(sb, gb + kk);
            cp16(sb + 8, gb + kk + 8);
            cp_commit();
        }
        int cb = ck % kStages;
        const __nv_bfloat16* Ab = As + cb * kTileElems;
        const __nv_bfloat16* Bb = Bs + cb * kTileElems;
        for (int k16 = 0; k16 < kBK; k16 += 16) {
            uint32_t afr[2][4];
            for (int mi = 0; mi < 2; mi++) {
                const __nv_bfloat16* pa =
                    Ab + (m0 + mi * 16 + (lane & 15)) * kLds + k16 + ((lane >> 4) & 1) * 8;
                ldmat_x4(afr[mi][0], afr[mi][1], afr[mi][2], afr[mi][3], pa);
            }
            uint32_t bfr[4][4];
            int quad = lane >> 3;
            int l7 = lane & 7;
            for (int g = 0; g < 4; g++) {
                const __nv_bfloat16* pb =
                    Bb + (n0 + g * 16 + ((quad >> 1) & 1) * 8 + l7) * kLds + k16 + (quad & 1) * 8;
                ldmat_x4(bfr[g][0], bfr[g][1], bfr[g][2], bfr[g][3], pb);
            }
            for (int mi = 0; mi < 2; mi++) {
                for (int nt = 0; nt < 8; nt++) {
                    int g = nt >> 1;
                    int ph = nt & 1;
                    mma_bf16(acc[mi][nt], afr[mi], bfr[g][ph * 2], bfr[g][ph * 2 + 1]);
                }
            }
        }
    }

    float sqa[2][2];
    for (int mi = 0; mi < 2; mi++) {
        for (int h = 0; h < 2; h++) {
            sqa[mi][h] = g_rowsq[by * kBM + m0 + mi * 16 + (lane >> 2) + h * 8];
        }
    }
    float sqb[8][2];
    for (int nt = 0; nt < 8; nt++) {
        for (int j = 0; j < 2; j++) {
            sqb[nt][j] = g_rowsq[bx * kBM + n0 + nt * 8 + 2 * (lane & 3) + j];
        }
    }

    float s2[kNS];
    for (int q = 0; q < kNS; q++) {
        s2[q] = g_s2[q];
    }
    int cnt[kNS];
    for (int q = 0; q < kNS; q++) {
        cnt[q] = 0;
    }
    for (int mi = 0; mi < 2; mi++) {
        for (int nt = 0; nt < 8; nt++) {
            for (int q4 = 0; q4 < 4; q4++) {
                int h = q4 >> 1;
                int j = q4 & 1;
                float d2 = sqa[mi][h] + sqb[nt][j] - 2.0f * acc[mi][nt][q4];
                for (int q = 0; q < kNS; q++) {
                    cnt[q] += (d2 < s2[q]) ? 1 : 0;
                }
            }
        }
    }

    __shared__ int scnt[kNS];
    if (tid < kNS) {
        scnt[tid] = 0;
    }
    __syncthreads();
    for (int q = 0; q < kNS; q++) {
        int vv = __reduce_add_sync(0xffffffffu, cnt[q]);
        if (lane == 0) {
            atomicAdd(&scnt[q], vv);
        }
    }
    __syncthreads();
    if (tid < kNS) {
        long long total = (long long)scnt[tid] * (long long)mult;
        atomicAdd(&g_corr_cnt[tid], (unsigned long long)total);
    }
}

// ---------------- K6: slopes + softmax-weighted output (one warp) ----------------
__global__ void k_final(const float* __restrict__ simp, float* __restrict__ outp) {
    int lane = threadIdx.x;
    bool act = lane < kNS;

    double lg = 0.0, yb = 0.0, yc = 0.0, yi = 0.0;
    if (act) {
        int scl = g_scales[lane];
        lg = log((double)(float)scl);
        yb = log((double)g_box_cnt[lane]);
        yc = log((double)g_corr_cnt[lane]);
        unsigned long long tot = 0;
        for (int b = 0; b < scl; b++) {
            tot += g_hist[lane][b];
        }
        double ent = 0.0;
        for (int b = 0; b < scl; b++) {
            if (g_hist[lane][b] > 0) {
                double p = (double)g_hist[lane][b] / (double)tot;
                ent -= p * log(p);
            }
        }
        yi = ent;
    }

    // least-squares slope via raw sums (n = kNS)
    double sx = lg, sxx = lg * lg;
    double sb = yb, sbx = lg * yb;
    double sc = yc, scx = lg * yc;
    double si = yi, six = lg * yi;
    for (int o = 16; o > 0; o >>= 1) {
        sx  += __shfl_down_sync(0xffffffffu, sx,  o);
        sxx += __shfl_down_sync(0xffffffffu, sxx, o);
        sb  += __shfl_down_sync(0xffffffffu, sb,  o);
        sbx += __shfl_down_sync(0xffffffffu, sbx, o);
        sc  += __shfl_down_sync(0xffffffffu, sc,  o);
        scx += __shfl_down_sync(0xffffffffu, scx, o);
        si  += __shfl_down_sync(0xffffffffu, si,  o);
        six += __shfl_down_sync(0xffffffffu, six, o);
    }

    // softmax weights
    float sv = act ? simp[lane] : -3.0e38f;
    float mx = sv;
    for (int o = 16; o > 0; o >>= 1) {
        mx = fmaxf(mx, __shfl_down_sync(0xffffffffu, mx, o));
    }
    mx = __shfl_sync(0xffffffffu, mx, 0);
    double wv = act ? exp((double)(sv - mx)) : 0.0;
    double wsum = wv;
    for (int o = 16; o > 0; o >>= 1) {
        wsum += __shfl_down_sync(0xffffffffu, wsum, o);
    }
    double w0 = __shfl_sync(0xffffffffu, wv, 0);
    double w1 = __shfl_sync(0xffffffffu, wv, 1);
    double w2 = __shfl_sync(0xffffffffu, wv, 2);

    if (lane == 0) {
        double n = (double)kNS;
        double den = sxx - sx * sx / n;
        double box_dim  = -((sbx - sx * sb / n) / den);
        double corr_dim =  ((scx - sx * sc / n) / den);
        double info_dim =  ((six - sx * si / n) / den);
        double o = (w0 * box_dim + w1 * corr_dim + w2 * info_dim) / wsum;
        outp[0] = (float)o;
    }
}

// ---------------- launch ----------------
extern "C" void kernel_launch(void* const* d_in, const int* in_sizes, int n_in,
                              void* d_out, int out_size) {
    const float* x = (const float*)d_in[0];
    const float* sp = (const float*)d_in[1];
    const float* simp = (const float*)d_in[2];
    float* outp = (float*)d_out;

    cudaFuncSetAttribute(k_corr, cudaFuncAttributeMaxDynamicSharedMemorySize, kSmemBytes);

    k_init<<<1, 256>>>();
    k_statscvt<<<kN / 8, 256>>>(x);
    k_setup<<<1, 32>>>(sp);
    k_boxhist<<<kN / 8, 256>>>(x);
    int ntiles = kN / kBM;
    k_corr<<<ntiles * (ntiles + 1) / 2, 256, kSmemBytes>>>();
    k_final<<<1, 32>>>(simp, outp);
}

// round 10
// speedup vs baseline: 4.6446x; 1.1475x over previous
#include <cuda_runtime.h>
#include <cuda_bf16.h>
#include <math.h>
#include <stdint.h>

constexpr int kN   = 8192;   // points
constexpr int kD   = 256;    // dim
constexpr int kNS  = 5;      // scales
constexpr int kBM  = 128;    // block tile (M and N)
constexpr int kBK  = 32;     // k tile
constexpr int kLds = 40;     // smem row stride in bf16 elems (32 + 8 pad)
constexpr int kStages = 3;
constexpr int kTileElems = kBM * kLds;                       // per matrix per stage
constexpr int kSmemBytes = kStages * kTileElems * 2 * 2;     // A+B, bf16 -> 61440

// ---------------- device scratch (no allocations allowed) ----------------
__device__ double g_sumsq;
__device__ double g_colsum[kD];
__device__ unsigned int g_minbits;
__device__ unsigned int g_maxbits;
__device__ float  g_rowsq[kN];
__device__ __nv_bfloat16 g_xb[kN * kD];
__device__ int    g_scales[kNS];
__device__ float  g_s2[kNS];
__device__ float  g_boxthr[kNS];
__device__ float  g_hmin;
__device__ float  g_hrange;
__device__ unsigned long long g_box_cnt[kNS];
__device__ unsigned long long g_corr_cnt[kNS];
__device__ unsigned long long g_hist[kNS][16];

__device__ __forceinline__ unsigned f2mono(float f) {
    unsigned u = __float_as_uint(f);
    return (u & 0x80000000u) ? ~u : (u | 0x80000000u);
}
__device__ __forceinline__ float mono2f(unsigned u) {
    unsigned b = (u & 0x80000000u) ? (u & 0x7fffffffu) : ~u;
    return __uint_as_float(b);
}

// ---------------- K0: zero scratch (graph replays => must re-init) ----------------
__global__ void k_init() {
    int t = threadIdx.x;
    if (t == 0) {
        g_sumsq = 0.0;
        g_minbits = 0xFFFFFFFFu;
        g_maxbits = 0u;
    }
    if (t < kD) {
        g_colsum[t] = 0.0;
    }
    if (t < kNS) {
        g_box_cnt[t] = 0ull;
        g_corr_cnt[t] = 0ull;
    }
    if (t < kNS * 16) {
        ((unsigned long long*)g_hist)[t] = 0ull;
    }
}

// ---------------- K1: fused stats + bf16 conversion + row norms ----------------
// grid 512 x 256; each block handles 16 rows (2 iterations of 8); column sums
// accumulate in registers, reduced via conflict-free transposed smem store.
__global__ void k_statscvt(const float* __restrict__ x) {
    __shared__ double s2col[8][kD];
    __shared__ double ssq[256];
    __shared__ unsigned smin[256];
    __shared__ unsigned smax[256];
    int t = threadIdx.x;
    int w = t >> 5;
    int lane = t & 31;

    double colacc[8];
    for (int i = 0; i < 8; i++) {
        colacc[i] = 0.0;
    }
    double lq = 0.0;
    unsigned lmin = 0xFFFFFFFFu;
    unsigned lmax = 0u;

    for (int it = 0; it < 2; it++) {
        int row = (blockIdx.x * 2 + it) * 8 + w;
        const float4* xr = (const float4*)(x + row * kD);
        float4 a = xr[lane];
        float4 b = xr[lane + 32];

        float s = a.x * a.x + a.y * a.y + a.z * a.z + a.w * a.w
                + b.x * b.x + b.y * b.y + b.z * b.z + b.w * b.w;
        for (int o = 16; o > 0; o >>= 1) {
            s += __shfl_down_sync(0xffffffffu, s, o);
        }
        if (lane == 0) {
            g_rowsq[row] = s;
        }

        __nv_bfloat162* dst = (__nv_bfloat162*)(g_xb + row * kD);
        dst[lane * 2 + 0] = __floats2bfloat162_rn(a.x, a.y);
        dst[lane * 2 + 1] = __floats2bfloat162_rn(a.z, a.w);
        dst[64 + lane * 2 + 0] = __floats2bfloat162_rn(b.x, b.y);
        dst[64 + lane * 2 + 1] = __floats2bfloat162_rn(b.z, b.w);

        colacc[0] += a.x; colacc[1] += a.y; colacc[2] += a.z; colacc[3] += a.w;
        colacc[4] += b.x; colacc[5] += b.y; colacc[6] += b.z; colacc[7] += b.w;

        lq += (double)a.x * a.x + (double)a.y * a.y + (double)a.z * a.z + (double)a.w * a.w
            + (double)b.x * b.x + (double)b.y * b.y + (double)b.z * b.z + (double)b.w * b.w;
        unsigned m1 = min(min(f2mono(a.x), f2mono(a.y)), min(f2mono(a.z), f2mono(a.w)));
        unsigned m2 = min(min(f2mono(b.x), f2mono(b.y)), min(f2mono(b.z), f2mono(b.w)));
        lmin = min(lmin, min(m1, m2));
        unsigned x1 = max(max(f2mono(a.x), f2mono(a.y)), max(f2mono(a.z), f2mono(a.w)));
        unsigned x2 = max(max(f2mono(b.x), f2mono(b.y)), max(f2mono(b.z), f2mono(b.w)));
        lmax = max(lmax, max(x1, x2));
    }

    // transposed store: warp w, lane l owns cols l*4+j and 128+l*4+j (no conflicts)
    for (int j = 0; j < 4; j++) {
        s2col[w][lane * 4 + j] = colacc[j];
        s2col[w][128 + lane * 4 + j] = colacc[4 + j];
    }
    ssq[t] = lq;
    smin[t] = lmin;
    smax[t] = lmax;
    __syncthreads();

    double csum = s2col[0][t] + s2col[1][t] + s2col[2][t] + s2col[3][t]
                + s2col[4][t] + s2col[5][t] + s2col[6][t] + s2col[7][t];
    atomicAdd(&g_colsum[t], csum);

    for (int o = 128; o > 0; o >>= 1) {
        if (t < o) {
            ssq[t] += ssq[t + o];
            smin[t] = min(smin[t], smin[t + o]);
            smax[t] = max(smax[t], smax[t + o]);
        }
        __syncthreads();
    }
    if (t == 0) {
        atomicAdd(&g_sumsq, ssq[0]);
        atomicMin(&g_minbits, smin[0]);
        atomicMax(&g_maxbits, smax[0]);
    }
}

// ---------------- K2: scales + thresholds (single warp) ----------------
__global__ void k_setup(const float* __restrict__ scale_params) {
    int lane = threadIdx.x;

    double p = g_colsum[lane] + g_colsum[lane + 32] + g_colsum[lane + 64] + g_colsum[lane + 96]
             + g_colsum[lane + 128] + g_colsum[lane + 160] + g_colsum[lane + 192] + g_colsum[lane + 224];
    for (int o = 16; o > 0; o >>= 1) {
        p += __shfl_down_sync(0xffffffffu, p, o);
    }
    double tot = __shfl_sync(0xffffffffu, p, 0);

    int scl = 0;
    if (lane < kNS) {
        double nd = (double)kN * (double)kD;
        double mean = tot / nd;
        double var = (g_sumsq - nd * mean * mean) / (nd - 1.0);
        double sf = sqrt(var) / mean;
        sf = fmin(fmax(sf, 0.5), 2.0);
        double v = exp((double)scale_params[lane]) * sf;
        v = fmin(fmax(v, 2.0), 16.0);
        scl = (int)v;
        g_scales[lane] = scl;
        g_s2[lane] = (float)(scl * scl);
    }
    if (lane == 0) {
        float mn = mono2f(g_minbits);
        float mx = mono2f(g_maxbits);
        g_hmin = mn;
        g_hrange = mx - mn;
    }

    for (int i = 0; i < kNS; i++) {
        int s = __shfl_sync(0xffffffffu, scl, i);
        int n = (kD / s) * s;
        double q = 0.0;
        for (int j = lane; j < n; j += 32) {
            q += g_colsum[j];
        }
        for (int o = 16; o > 0; o >>= 1) {
            q += __shfl_down_sync(0xffffffffu, q, o);
        }
        if (lane == 0) {
            g_boxthr[i] = (float)(q / ((double)kN * (double)n));
        }
    }
}

// ---------------- K3: fused box counting + histograms (packed-key match) ----------------
__global__ void k_boxhist(const float* __restrict__ x) {
    __shared__ float pf[8][kD + 8];
    __shared__ int sh[kNS][16];
    __shared__ int sbox[kNS];
    __shared__ float sthr[kNS];
    __shared__ int sscl[kNS];
    int t = threadIdx.x;
    int w = t >> 5;
    int lane = t & 31;
    int row = blockIdx.x * 8 + w;

    if (t < kNS * 16) {
        ((int*)sh)[t] = 0;
    }
    if (t < kNS) {
        sbox[t] = 0;
        sthr[t] = g_boxthr[t];
        sscl[t] = g_scales[t];
    }

    const float4* xr = (const float4*)(x + row * kD);
    float4 va = xr[lane * 2];
    float4 vb = xr[lane * 2 + 1];
    float v[8];
    v[0] = va.x; v[1] = va.y; v[2] = va.z; v[3] = va.w;
    v[4] = vb.x; v[5] = vb.y; v[6] = vb.z; v[7] = vb.w;

    {
        float run = 0.f;
        float incl[8];
        for (int i = 0; i < 8; i++) {
            run += v[i];
            incl[i] = run;
        }
        float tsum = run;
        for (int o = 1; o < 32; o <<= 1) {
            float y = __shfl_up_sync(0xffffffffu, tsum, o);
            if (lane >= o) {
                tsum += y;
            }
        }
        float basep = tsum - run;
        for (int i = 0; i < 8; i++) {
            pf[w][lane * 8 + i + 1] = basep + incl[i];
        }
        if (lane == 0) {
            pf[w][0] = 0.f;
        }
    }
    __syncthreads();

    // box counting via prefix differences (skip duplicate scales)
    for (int si = 0; si < kNS; si++) {
        int s = sscl[si];
        if (si > 0 && s == sscl[si - 1]) {
            continue;
        }
        float thr = sthr[si];
        int m = kD / s;
        float inv = 1.0f / (float)s;
        int cnt = 0;
        for (int g = lane; g < m; g += 32) {
            float sum = pf[w][g * s + s] - pf[w][g * s];
            cnt += (sum * inv > thr) ? 1 : 0;
        }
        cnt = __reduce_add_sync(0xffffffffu, cnt);
        if (lane == 0) {
            atomicAdd(&sbox[si], cnt);
        }
    }

    // histograms: pack all 5 bins into one key, single match_any per element
    float mn = g_hmin;
    float rng = g_hrange;
    float invr = (rng > 0.f) ? (1.0f / rng) : 0.f;
    float fs[kNS];
    int scl[kNS];
    for (int si = 0; si < kNS; si++) {
        scl[si] = sscl[si];
        fs[si] = (float)scl[si];
    }
    for (int i = 0; i < 8; i++) {
        float u = (v[i] - mn) * invr;
        int b[kNS];
        unsigned key = 0;
#pragma unroll
        for (int si = 0; si < kNS; si++) {
            int bb = (int)(u * fs[si]);
            bb = min(bb, scl[si] - 1);
            bb = max(bb, 0);
            b[si] = bb;
            key |= (unsigned)bb << (si * 4);
        }
        unsigned msk = __match_any_sync(0xffffffffu, key);
        if (lane == (__ffs(msk) - 1)) {
            int pc = __popc(msk);
#pragma unroll
            for (int si = 0; si < kNS; si++) {
                atomicAdd(&sh[si][b[si]], pc);
            }
        }
    }
    __syncthreads();
    // writeback: box uses duplicate-scale canonicalization; hist written directly
    if (t < kNS) {
        int c = t;
        while (c > 0 && sscl[c] == sscl[c - 1]) {
            c--;
        }
        atomicAdd(&g_box_cnt[t], (unsigned long long)sbox[c]);
    }
    if (t < kNS * 16) {
        int vv = ((int*)sh)[t];
        if (vv != 0) {
            atomicAdd(&((unsigned long long*)g_hist)[t], (unsigned long long)vv);
        }
    }
}

// ---------------- K5: pairwise distance counts via bf16 tensor cores ----------------
__device__ __forceinline__ void ldmat_x4(uint32_t& r0, uint32_t& r1,
                                         uint32_t& r2, uint32_t& r3,
                                         const __nv_bfloat16* p) {
    uint32_t addr = (uint32_t)__cvta_generic_to_shared(p);
    asm volatile(
        "ldmatrix.sync.aligned.m8n8.x4.shared.b16 {%0,%1,%2,%3}, [%4];"
        : "=r"(r0), "=r"(r1), "=r"(r2), "=r"(r3)
        : "r"(addr));
}

__device__ __forceinline__ void mma_bf16(float* c, const uint32_t* a,
                                         uint32_t b0, uint32_t b1) {
    asm volatile(
        "mma.sync.aligned.m16n8k16.row.col.f32.bf16.bf16.f32 "
        "{%0,%1,%2,%3}, {%4,%5,%6,%7}, {%8,%9}, {%0,%1,%2,%3};"
        : "+f"(c[0]), "+f"(c[1]), "+f"(c[2]), "+f"(c[3])
        : "r"(a[0]), "r"(a[1]), "r"(a[2]), "r"(a[3]), "r"(b0), "r"(b1));
}

__device__ __forceinline__ void cp16(void* sp, const void* gp) {
    uint32_t a = (uint32_t)__cvta_generic_to_shared(sp);
    asm volatile("cp.async.ca.shared.global [%0], [%1], 16;" :: "r"(a), "l"(gp));
}
__device__ __forceinline__ void cp_commit() {
    asm volatile("cp.async.commit_group;");
}
template <int n>
__device__ __forceinline__ void cp_wait() {
    asm volatile("cp.async.wait_group %0;" :: "n"(n));
}

__global__ void __launch_bounds__(256, 2) k_corr() {
    extern __shared__ __align__(16) __nv_bfloat16 smem[];
    __nv_bfloat16* As = smem;                              // [kStages][kBM][kLds]
    __nv_bfloat16* Bs = smem + kStages * kTileElems;       // [kStages][kBM][kLds]

    int kblk = blockIdx.x;
    int r = (int)((sqrtf(8.0f * (float)kblk + 1.0f) - 1.0f) * 0.5f);
    while ((r + 1) * (r + 2) / 2 <= kblk) {
        r++;
    }
    while (r * (r + 1) / 2 > kblk) {
        r--;
    }
    int c = kblk - r * (r + 1) / 2;
    int bx = r;
    int by = c;
    int mult = (bx == by) ? 1 : 2;

    const __nv_bfloat16* Arows = g_xb + by * kBM * kD;
    const __nv_bfloat16* Brows = g_xb + bx * kBM * kD;

    int tid = threadIdx.x;
    int lane = tid & 31;
    int wid = tid >> 5;
    int warpM = wid & 3;
    int warpN = wid >> 2;
    int m0 = warpM * 32;
    int n0 = warpN * 64;

    int srow = tid >> 1;
    int sq = (tid & 1) * 2;
    const __nv_bfloat16* ga = Arows + srow * kD + sq * 8;
    const __nv_bfloat16* gb = Brows + srow * kD + sq * 8;
    int soff = srow * kLds + sq * 8;

    float acc[2][8][4];
    for (int i = 0; i < 2; i++) {
        for (int j = 0; j < 8; j++) {
            for (int q = 0; q < 4; q++) {
                acc[i][j][q] = 0.f;
            }
        }
    }

    constexpr int kChunks = kD / kBK;   // 8

    for (int ps = 0; ps < 2; ps++) {
        int kk = ps * kBK;
        __nv_bfloat16* sa = As + ps * kTileElems + soff;
        __nv_bfloat16* sb = Bs + ps * kTileElems + soff;
        cp16(sa, ga + kk);
        cp16(sa + 8, ga + kk + 8);
        cp16(sb, gb + kk);
        cp16(sb + 8, gb + kk + 8);
        cp_commit();
    }

    for (int ck = 0; ck < kChunks; ck++) {
        if (ck < kChunks - 1) {
            cp_wait<1>();
        } else {
            cp_wait<0>();
        }
        __syncthreads();
        if (ck + 2 < kChunks) {
            int nb = (ck + 2) % kStages;
            int kk = (ck + 2) * kBK;
            __nv_bfloat16* sa = As + nb * kTileElems + soff;
            __nv_bfloat16* sb = Bs + nb * kTileElems + soff;
            cp16(sa, ga + kk);
            cp16(sa + 8, ga + kk + 8);
            cp16(sb, gb + kk);
            cp16(sb + 8, gb + kk + 8);
            cp_commit();
        }
        int cb = ck % kStages;
        const __nv_bfloat16* Ab = As + cb * kTileElems;
        const __nv_bfloat16* Bb = Bs + cb * kTileElems;
        for (int k16 = 0; k16 < kBK; k16 += 16) {
            uint32_t afr[2][4];
            for (int mi = 0; mi < 2; mi++) {
                const __nv_bfloat16* pa =
                    Ab + (m0 + mi * 16 + (lane & 15)) * kLds + k16 + ((lane >> 4) & 1) * 8;
                ldmat_x4(afr[mi][0], afr[mi][1], afr[mi][2], afr[mi][3], pa);
            }
            uint32_t bfr[4][4];
            int quad = lane >> 3;
            int l7 = lane & 7;
            for (int g = 0; g < 4; g++) {
                const __nv_bfloat16* pb =
                    Bb + (n0 + g * 16 + ((quad >> 1) & 1) * 8 + l7) * kLds + k16 + (quad & 1) * 8;
                ldmat_x4(bfr[g][0], bfr[g][1], bfr[g][2], bfr[g][3], pb);
            }
            for (int mi = 0; mi < 2; mi++) {
                for (int nt = 0; nt < 8; nt++) {
                    int g = nt >> 1;
                    int ph = nt & 1;
                    mma_bf16(acc[mi][nt], afr[mi], bfr[g][ph * 2], bfr[g][ph * 2 + 1]);
                }
            }
        }
    }

    float sqa[2][2];
    for (int mi = 0; mi < 2; mi++) {
        for (int h = 0; h < 2; h++) {
            sqa[mi][h] = g_rowsq[by * kBM + m0 + mi * 16 + (lane >> 2) + h * 8];
        }
    }
    float sqb[8][2];
    for (int nt = 0; nt < 8; nt++) {
        for (int j = 0; j < 2; j++) {
            sqb[nt][j] = g_rowsq[bx * kBM + n0 + nt * 8 + 2 * (lane & 3) + j];
        }
    }

    float s2[kNS];
    for (int q = 0; q < kNS; q++) {
        s2[q] = g_s2[q];
    }
    int cnt[kNS];
    for (int q = 0; q < kNS; q++) {
        cnt[q] = 0;
    }
    for (int mi = 0; mi < 2; mi++) {
        for (int nt = 0; nt < 8; nt++) {
            for (int q4 = 0; q4 < 4; q4++) {
                int h = q4 >> 1;
                int j = q4 & 1;
                float d2 = sqa[mi][h] + sqb[nt][j] - 2.0f * acc[mi][nt][q4];
                for (int q = 0; q < kNS; q++) {
                    cnt[q] += (d2 < s2[q]) ? 1 : 0;
                }
            }
        }
    }

    __shared__ int scnt[kNS];
    if (tid < kNS) {
        scnt[tid] = 0;
    }
    __syncthreads();
    for (int q = 0; q < kNS; q++) {
        int vv = __reduce_add_sync(0xffffffffu, cnt[q]);
        if (lane == 0) {
            atomicAdd(&scnt[q], vv);
        }
    }
    __syncthreads();
    if (tid < kNS) {
        long long total = (long long)scnt[tid] * (long long)mult;
        atomicAdd(&g_corr_cnt[tid], (unsigned long long)total);
    }
}

// ---------------- K6: slopes + softmax-weighted output (one warp) ----------------
__global__ void k_final(const float* __restrict__ simp, float* __restrict__ outp) {
    int lane = threadIdx.x;
    bool act = lane < kNS;

    double lg = 0.0, yb = 0.0, yc = 0.0, yi = 0.0;
    if (act) {
        int scl = g_scales[lane];
        lg = log((double)(float)scl);
        yb = log((double)g_box_cnt[lane]);
        yc = log((double)g_corr_cnt[lane]);
        unsigned long long tot = 0;
        for (int b = 0; b < scl; b++) {
            tot += g_hist[lane][b];
        }
        double ent = 0.0;
        for (int b = 0; b < scl; b++) {
            if (g_hist[lane][b] > 0) {
                double p = (double)g_hist[lane][b] / (double)tot;
                ent -= p * log(p);
            }
        }
        yi = ent;
    }

    double sx = lg, sxx = lg * lg;
    double sb = yb, sbx = lg * yb;
    double sc = yc, scx = lg * yc;
    double si = yi, six = lg * yi;
    for (int o = 16; o > 0; o >>= 1) {
        sx  += __shfl_down_sync(0xffffffffu, sx,  o);
        sxx += __shfl_down_sync(0xffffffffu, sxx, o);
        sb  += __shfl_down_sync(0xffffffffu, sb,  o);
        sbx += __shfl_down_sync(0xffffffffu, sbx, o);
        sc  += __shfl_down_sync(0xffffffffu, sc,  o);
        scx += __shfl_down_sync(0xffffffffu, scx, o);
        si  += __shfl_down_sync(0xffffffffu, si,  o);
        six += __shfl_down_sync(0xffffffffu, six, o);
    }

    float sv = act ? simp[lane] : -3.0e38f;
    float mx = sv;
    for (int o = 16; o > 0; o >>= 1) {
        mx = fmaxf(mx, __shfl_down_sync(0xffffffffu, mx, o));
    }
    mx = __shfl_sync(0xffffffffu, mx, 0);
    double wv = act ? exp((double)(sv - mx)) : 0.0;
    double wsum = wv;
    for (int o = 16; o > 0; o >>= 1) {
        wsum += __shfl_down_sync(0xffffffffu, wsum, o);
    }
    double w0 = __shfl_sync(0xffffffffu, wv, 0);
    double w1 = __shfl_sync(0xffffffffu, wv, 1);
    double w2 = __shfl_sync(0xffffffffu, wv, 2);

    if (lane == 0) {
        double n = (double)kNS;
        double den = sxx - sx * sx / n;
        double box_dim  = -((sbx - sx * sb / n) / den);
        double corr_dim =  ((scx - sx * sc / n) / den);
        double info_dim =  ((six - sx * si / n) / den);
        double o = (w0 * box_dim + w1 * corr_dim + w2 * info_dim) / wsum;
        outp[0] = (float)o;
    }
}

// ---------------- launch ----------------
extern "C" void kernel_launch(void* const* d_in, const int* in_sizes, int n_in,
                              void* d_out, int out_size) {
    const float* x = (const float*)d_in[0];
    const float* sp = (const float*)d_in[1];
    const float* simp = (const float*)d_in[2];
    float* outp = (float*)d_out;

    cudaFuncSetAttribute(k_corr, cudaFuncAttributeMaxDynamicSharedMemorySize, kSmemBytes);

    k_init<<<1, 256>>>();
    k_statscvt<<<512, 256>>>(x);
    k_setup<<<1, 32>>>(sp);
    k_boxhist<<<kN / 8, 256>>>(x);
    int ntiles = kN / kBM;
    k_corr<<<ntiles * (ntiles + 1) / 2, 256, kSmemBytes>>>();
    k_final<<<1, 32>>>(simp, outp);
}